// round 11
// baseline (speedup 1.0000x reference)
#include <cuda_runtime.h>
#include <cuda_bf16.h>
#include <cstdint>

#define NODES 50000
#define EDGES 800000
#define HID   128
#define CAP   128
#define OVFMAX 65536
#define NTILES 391            // ceil(50000/128)

// ---------------------------------------------------------------------------
// Device-global scratch (no allocations allowed)
// ---------------------------------------------------------------------------
__device__ float g_h2[(size_t)NODES * HID];
__device__ float g_P[(size_t)NODES * HID];
__device__ float g_Q[(size_t)NODES * HID];
__device__ int   g_cnt[NODES];
__device__ int   g_bucket[(size_t)NODES * CAP];
__device__ int2  g_ovf[OVFMAX];
__device__ int   g_novf;

// S aggregate as bf16 hi/lo images: per 128-row tile, 32 KB contiguous;
// element (r,k) at byte off = r*256 + ((k>>6)<<7) + (((k&63)<<1) ^ ((r&7)<<4)).
__device__ uint4 g_sHi[(size_t)NTILES * 2048];
__device__ uint4 g_sLo[(size_t)NTILES * 2048];

// Weight images (transposed, hi block 32KB then lo block 32KB)
__device__ uint4 g_iWin[4096];
__device__ uint4 g_iW1a[4096];
__device__ uint4 g_iW1b[4096];
__device__ uint4 g_iW2 [4096];

// ---------------------------------------------------------------------------
__device__ __forceinline__ uint32_t smem_u32(const void* p) {
    uint32_t a;
    asm("{ .reg .u64 t; cvta.to.shared.u64 t, %1; cvt.u32.u64 %0, t; }"
        : "=r"(a) : "l"(p));
    return a;
}
__device__ __forceinline__ unsigned packbf(float x, float y) {
    __nv_bfloat162 t = __floats2bfloat162_rn(x, y);
    return *reinterpret_cast<unsigned*>(&t);
}
__device__ __forceinline__ void ldsm4(unsigned* r, uint32_t addr) {
    asm volatile("ldmatrix.sync.aligned.m8n8.x4.shared.b16 {%0,%1,%2,%3}, [%4];"
                 : "=r"(r[0]), "=r"(r[1]), "=r"(r[2]), "=r"(r[3]) : "r"(addr));
}
__device__ __forceinline__ void mma16816(float* d, const unsigned* a,
                                         unsigned b0, unsigned b1) {
    asm volatile(
        "mma.sync.aligned.m16n8k16.row.col.f32.bf16.bf16.f32 "
        "{%0,%1,%2,%3},{%4,%5,%6,%7},{%8,%9},{%0,%1,%2,%3};"
        : "+f"(d[0]), "+f"(d[1]), "+f"(d[2]), "+f"(d[3])
        : "r"(a[0]), "r"(a[1]), "r"(a[2]), "r"(a[3]), "r"(b0), "r"(b1));
}
__device__ __forceinline__ void cpa16(uint32_t dst, const void* src) {
    asm volatile("cp.async.cg.shared.global [%0], [%1], 16;"
                 :: "r"(dst), "l"(src));
}
__device__ __forceinline__ void cpa16z(uint32_t dst, const void* src, int sz) {
    asm volatile("cp.async.cg.shared.global [%0], [%1], 16, %2;"
                 :: "r"(dst), "l"(src), "r"(sz));
}
#define CP_COMMIT() asm volatile("cp.async.commit_group;" ::: "memory")
#define CP_WAIT0()  asm volatile("cp.async.wait_group 0;" ::: "memory")

__device__ __forceinline__ uint32_t img_off(int r, int k) {
    return (uint32_t)r * 256 + ((k >> 6) << 7) + ((((k & 63) << 1)) ^ ((r & 7) << 4));
}
__device__ __forceinline__ uint32_t f32_off(int r, int cc) {
    return (uint32_t)r * 512 +
           (((uint32_t)cc * 16) ^ ((r & 7) << 4) ^ ((cc >> 3) << 4));
}

// ---------------------------------------------------------------------------
// Prep: weight images
// ---------------------------------------------------------------------------
__device__ __forceinline__ void img_write(uint4* img, int n, int k, float v) {
    __nv_bfloat16 hi = __float2bfloat16(v);
    float hf = __bfloat162float(hi);
    __nv_bfloat16 lo = __float2bfloat16(v - hf);
    uint32_t off = img_off(n, k);
    __nv_bfloat16* p = (__nv_bfloat16*)img;
    p[off >> 1]               = hi;
    p[128 * 128 + (off >> 1)] = lo;
}

__global__ void __launch_bounds__(256)
prep_kernel(const float* __restrict__ W_in, const float* __restrict__ W1,
            const float* __restrict__ W2)
{
    int idx = blockIdx.x * blockDim.x + threadIdx.x;
    int n = (idx >> 7) & 127, k = idx & 127;
    if (idx < 16384) {
        img_write(g_iWin, n, k, W_in[k * 128 + n]);
    } else if (idx < 32768) {
        img_write(g_iW1a, n, k, W1[k * 128 + n]);
    } else if (idx < 49152) {
        img_write(g_iW1b, n, k, W1[(128 + k) * 128 + n]);
    } else if (idx < 65536) {
        img_write(g_iW2, n, k, W2[k * 128 + n]);
    }
}

// ---------------------------------------------------------------------------
// Mainloop with frag reuse: per k-step load Ah/Al/Bh/Bl frags once (8 ldsm4),
// issue 24 HMMAs (AhBh + AlBh + AhBl).
// ---------------------------------------------------------------------------
__device__ __forceinline__ void tile_mainloop(
    float acc[2][4][4], uint32_t aHi, uint32_t aLo, uint32_t bHi, uint32_t bLo,
    int warpM, int warpN, int fi, int fswz, int fk8)
{
#pragma unroll
    for (int mt = 0; mt < 2; ++mt)
#pragma unroll
        for (int ns = 0; ns < 4; ++ns)
#pragma unroll
            for (int e = 0; e < 4; ++e) acc[mt][ns][e] = 0.f;

#pragma unroll
    for (int ks = 0; ks < 8; ++ks) {
        const int k8 = ks * 16 + fk8;
        const uint32_t koff = ((k8 >> 6) << 7) + (((k8 & 63) << 1) ^ fswz);
        unsigned ah[2][4], al[2][4], bh[2][4], bl[2][4];
#pragma unroll
        for (int mt = 0; mt < 2; ++mt) {
            uint32_t ra = (uint32_t)(warpM * 32 + mt * 16 + fi) * 256 + koff;
            ldsm4(ah[mt], aHi + ra);
            ldsm4(al[mt], aLo + ra);
        }
#pragma unroll
        for (int nt = 0; nt < 2; ++nt) {
            uint32_t rb = (uint32_t)(warpN * 32 + nt * 16 + fi) * 256 + koff;
            ldsm4(bh[nt], bHi + rb);
            ldsm4(bl[nt], bLo + rb);
        }
#pragma unroll
        for (int mt = 0; mt < 2; ++mt)
#pragma unroll
            for (int nt = 0; nt < 2; ++nt) {
                mma16816(acc[mt][nt * 2],     ah[mt], bh[nt][0], bh[nt][2]);
                mma16816(acc[mt][nt * 2 + 1], ah[mt], bh[nt][1], bh[nt][3]);
                mma16816(acc[mt][nt * 2],     al[mt], bh[nt][0], bh[nt][2]);
                mma16816(acc[mt][nt * 2 + 1], al[mt], bh[nt][1], bh[nt][3]);
                mma16816(acc[mt][nt * 2],     ah[mt], bl[nt][0], bl[nt][2]);
                mma16816(acc[mt][nt * 2 + 1], ah[mt], bl[nt][1], bl[nt][3]);
            }
    }
}

// fp32 epilogue (optional rowcnt-scaled bias + relu)
__device__ __forceinline__ void epi_f32(
    float acc[2][4][4], float* __restrict__ C, const float* __restrict__ bias,
    const int* __restrict__ rowcnt, int m0, int M, int do_relu,
    int warpM, int warpN, int L)
{
#pragma unroll
    for (int mt = 0; mt < 2; ++mt) {
        int gr0 = m0 + warpM * 32 + mt * 16 + (L >> 2);
        int gr1 = gr0 + 8;
        float sc0 = 1.f, sc1 = 1.f;
        if (rowcnt) {
            if (gr0 < M) sc0 = (float)rowcnt[gr0];
            if (gr1 < M) sc1 = (float)rowcnt[gr1];
        }
#pragma unroll
        for (int ns = 0; ns < 4; ++ns) {
            int c = warpN * 32 + ns * 8 + (L & 3) * 2;
            float b0 = bias ? bias[c]     : 0.f;
            float b1 = bias ? bias[c + 1] : 0.f;
            float v00 = acc[mt][ns][0] + sc0 * b0;
            float v01 = acc[mt][ns][1] + sc0 * b1;
            float v10 = acc[mt][ns][2] + sc1 * b0;
            float v11 = acc[mt][ns][3] + sc1 * b1;
            if (do_relu) {
                v00 = fmaxf(v00, 0.f); v01 = fmaxf(v01, 0.f);
                v10 = fmaxf(v10, 0.f); v11 = fmaxf(v11, 0.f);
            }
            if (gr0 < M) *(float2*)(C + (size_t)gr0 * 128 + c) = make_float2(v00, v01);
            if (gr1 < M) *(float2*)(C + (size_t)gr1 * 128 + c) = make_float2(v10, v11);
        }
    }
}

// ---------------------------------------------------------------------------
// gemm_hpq: fused x -> h (smem only) -> P, Q.
// smem: [buf 64K][S0 64K][S1 64K][WinHi 32K] = 224 KB.
//   buf:   x fp32 -> ximg (in place) -> himg (in place)
//   S0:    Win-lo (low 32K) during phase1; then W1b (64K) for phase3
//   S1:    W1a resident
//   WinHi: Win-hi resident
// ---------------------------------------------------------------------------
__global__ void __launch_bounds__(512, 1)
gemm_hpq(const float* __restrict__ x, const uint4* __restrict__ iWin,
         const uint4* __restrict__ iW1a, const uint4* __restrict__ iW1b,
         const float* __restrict__ b_in, const float* __restrict__ b1,
         float* __restrict__ P, float* __restrict__ Q, int M, int ntiles)
{
    extern __shared__ char smem[];
    const uint32_t sb   = smem_u32(smem);
    const uint32_t sBuf = sb;
    const uint32_t sS0  = sb + 65536;
    const uint32_t sS1  = sb + 131072;
    const uint32_t sWh  = sb + 196608;

    const int tid = threadIdx.x;
    const int wid = tid >> 5;
    const int L   = tid & 31;
    const int warpM = wid >> 2, warpN = wid & 3;
    const int fi = L & 15, fswz = (fi & 7) << 4, fk8 = (L >> 4) * 8;
    const int sr = tid >> 2, sq = tid & 3;   // convert mapping: 4 thr/row

    // Prologue copies: WinHi, WinLo->S0low, W1a->S1, x tile0 -> buf
    for (int i = tid; i < 2048; i += 512) {
        cpa16(sWh + i * 16, iWin + i);              // Win hi
        cpa16(sS0 + i * 16, iWin + 2048 + i);       // Win lo
    }
    for (int i = tid; i < 4096; i += 512) cpa16(sS1 + i * 16, iW1a + i);
    {
        int m0 = blockIdx.x * 128;
        for (int i = tid; i < 4096; i += 512) {
            int r = i >> 5, cc = i & 31;
            int gr = m0 + r;
            int sz = (gr < M) ? 16 : 0;
            const float* src = x + (size_t)(gr < M ? gr : 0) * 128 + cc * 4;
            cpa16z(sBuf + f32_off(r, cc), src, sz);
        }
    }
    CP_COMMIT();

    for (int tile = blockIdx.x; tile < ntiles; tile += gridDim.x) {
        const int m0 = tile * 128;
        CP_WAIT0();
        __syncthreads();   // x + Win-lo landed; prev-iter readers done

        // fp32 -> regs
        float4 v[8];
#pragma unroll
        for (int j = 0; j < 8; ++j)
            v[j] = *(const float4*)(smem + f32_off(sr, sq * 8 + j));
        __syncthreads();

        // convert in place: ximg hi (buf) / lo (buf+32K)
#pragma unroll
        for (int j = 0; j < 8; ++j) {
            float4 a = v[j];
            float hx = __bfloat162float(__float2bfloat16(a.x));
            float hy = __bfloat162float(__float2bfloat16(a.y));
            float hz = __bfloat162float(__float2bfloat16(a.z));
            float hw = __bfloat162float(__float2bfloat16(a.w));
            uint32_t off = img_off(sr, (sq * 8 + j) * 4);
            *(uint2*)(smem + off) =
                make_uint2(packbf(a.x, a.y), packbf(a.z, a.w));
            *(uint2*)(smem + 32768 + off) =
                make_uint2(packbf(a.x - hx, a.y - hy), packbf(a.z - hz, a.w - hw));
        }
        __syncthreads();

        // phase1: h = ximg @ Win  (Bh = WinHi resident, Bl = Win-lo in S0)
        float acc[2][4][4];
        tile_mainloop(acc, sBuf, sBuf + 32768, sWh, sS0,
                      warpM, warpN, fi, fswz, fk8);
        __syncthreads();   // everyone done reading ximg(buf) + WinLo(S0)

        // start W1b -> S0 (full 64K), overlaps epi-h + phase2
        for (int i = tid; i < 4096; i += 512) cpa16(sS0 + i * 16, iW1b + i);
        CP_COMMIT();

        // epi-h: relu(acc + b_in), split, write h image into buf (smem)
#pragma unroll
        for (int mt = 0; mt < 2; ++mt) {
            int r0 = warpM * 32 + mt * 16 + (L >> 2);
            int r1 = r0 + 8;
#pragma unroll
            for (int ns = 0; ns < 4; ++ns) {
                int c = warpN * 32 + ns * 8 + (L & 3) * 2;
                float b0 = b_in[c], b1v = b_in[c + 1];
                float v00 = fmaxf(acc[mt][ns][0] + b0, 0.f);
                float v01 = fmaxf(acc[mt][ns][1] + b1v, 0.f);
                float v10 = fmaxf(acc[mt][ns][2] + b0, 0.f);
                float v11 = fmaxf(acc[mt][ns][3] + b1v, 0.f);
                float h00 = __bfloat162float(__float2bfloat16(v00));
                float h01 = __bfloat162float(__float2bfloat16(v01));
                float h10 = __bfloat162float(__float2bfloat16(v10));
                float h11 = __bfloat162float(__float2bfloat16(v11));
                uint32_t o0 = img_off(r0, c), o1 = img_off(r1, c);
                *(unsigned*)(smem + o0)         = packbf(v00, v01);
                *(unsigned*)(smem + 32768 + o0) = packbf(v00 - h00, v01 - h01);
                *(unsigned*)(smem + o1)         = packbf(v10, v11);
                *(unsigned*)(smem + 32768 + o1) = packbf(v10 - h10, v11 - h11);
            }
        }
        __syncthreads();   // h image visible

        // phase2: P = himg @ W1a + b1
        tile_mainloop(acc, sBuf, sBuf + 32768, sS1, sS1 + 32768,
                      warpM, warpN, fi, fswz, fk8);
        epi_f32(acc, P, b1, nullptr, m0, M, 0, warpM, warpN, L);

        CP_WAIT0();        // W1b landed
        __syncthreads();

        // phase3: Q = himg @ W1b
        tile_mainloop(acc, sBuf, sBuf + 32768, sS0, sS0 + 32768,
                      warpM, warpN, fi, fswz, fk8);
        epi_f32(acc, Q, nullptr, nullptr, m0, M, 0, warpM, warpN, L);
        __syncthreads();   // everyone done reading buf(h) + S0(W1b)

        // next-tile copies: x -> buf, Win-lo -> S0 low
        int nxt = tile + gridDim.x;
        if (nxt < ntiles) {
            int m0n = nxt * 128;
            for (int i = tid; i < 4096; i += 512) {
                int r = i >> 5, cc = i & 31;
                int gr = m0n + r;
                int sz = (gr < M) ? 16 : 0;
                const float* src = x + (size_t)(gr < M ? gr : 0) * 128 + cc * 4;
                cpa16z(sBuf + f32_off(r, cc), src, sz);
            }
            for (int i = tid; i < 2048; i += 512)
                cpa16(sS0 + i * 16, iWin + 2048 + i);
        }
        CP_COMMIT();
    }
}

// ---------------------------------------------------------------------------
// gemm_b: image input, cp.async double-buffered; fp32 output.
// smem: [A0 64K][A1 64K][W 64K] = 192 KB.
// ---------------------------------------------------------------------------
__global__ void __launch_bounds__(512, 1)
gemm_b(const uint4* __restrict__ hiImg, const uint4* __restrict__ loImg,
       const uint4* __restrict__ Wimg, const float* __restrict__ bias,
       const int* __restrict__ rowcnt, float* __restrict__ C,
       int M, int ntiles, int do_relu)
{
    extern __shared__ char smem[];
    const uint32_t sb = smem_u32(smem);
    const uint32_t sW = sb + 131072;

    const int tid = threadIdx.x;
    const int wid = tid >> 5;
    const int L   = tid & 31;
    const int warpM = wid >> 2, warpN = wid & 3;
    const int fi = L & 15, fswz = (fi & 7) << 4, fk8 = (L >> 4) * 8;

    for (int i = tid; i < 4096; i += 512) cpa16(sW + i * 16, Wimg + i);
    {
        int t0 = blockIdx.x;
        if (t0 < ntiles) {
            const uint4* sH = hiImg + (size_t)t0 * 2048;
            const uint4* sL = loImg + (size_t)t0 * 2048;
            for (int i = tid; i < 2048; i += 512) {
                cpa16(sb + i * 16, sH + i);
                cpa16(sb + 32768 + i * 16, sL + i);
            }
        }
    }
    CP_COMMIT();

    int cur = 0;
    for (int tile = blockIdx.x; tile < ntiles; tile += gridDim.x) {
        CP_WAIT0();
        __syncthreads();

        int nxt = tile + gridDim.x;
        if (nxt < ntiles) {
            uint32_t dst = sb + (cur ^ 1) * 65536;
            const uint4* sH = hiImg + (size_t)nxt * 2048;
            const uint4* sL = loImg + (size_t)nxt * 2048;
            for (int i = tid; i < 2048; i += 512) {
                cpa16(dst + i * 16, sH + i);
                cpa16(dst + 32768 + i * 16, sL + i);
            }
        }
        CP_COMMIT();

        const uint32_t sAh = sb + cur * 65536;
        float acc[2][4][4];
        tile_mainloop(acc, sAh, sAh + 32768, sW, sW + 32768,
                      warpM, warpN, fi, fswz, fk8);

        epi_f32(acc, C, bias, rowcnt, tile * 128, M, do_relu, warpM, warpN, L);
        cur ^= 1;
    }
}

// ---------------------------------------------------------------------------
__global__ void __launch_bounds__(256)
zero_kernel()
{
    int idx = blockIdx.x * blockDim.x + threadIdx.x;
    int stride = gridDim.x * blockDim.x;
    for (int i = idx; i < NODES; i += stride) g_cnt[i] = 0;
    if (idx == 0) g_novf = 0;
}

__global__ void __launch_bounds__(256)
bucket_kernel(const int* __restrict__ ei)
{
    int e = blockIdx.x * blockDim.x + threadIdx.x;
    if (e >= EDGES) return;
    int s = ei[e];
    int d = ei[EDGES + e];
    int slot = atomicAdd(&g_cnt[d], 1);
    if (slot < CAP) {
        g_bucket[(size_t)d * CAP + slot] = s;
    } else {
        int o = atomicAdd(&g_novf, 1);
        if (o < OVFMAX) g_ovf[o] = make_int2(s, d);
    }
}

// Warp per node: S[d] = sum relu(P[d]+Q[src]); write S as bf16 hi/lo images.
__global__ void __launch_bounds__(256)
node_kernel()
{
    int d    = (blockIdx.x * blockDim.x + threadIdx.x) >> 5;
    int lane = threadIdx.x & 31;
    if (d >= NODES) return;

    int n = g_cnt[d];
    if (n > CAP) n = CAP;

    float4 p = ((const float4*)(g_P + (size_t)d * HID))[lane];
    float4 acc = make_float4(0.f, 0.f, 0.f, 0.f);
    const int* bkt = g_bucket + (size_t)d * CAP;
#pragma unroll 2
    for (int i = 0; i < n; ++i) {
        int s = __ldg(bkt + i);
        float4 q = ((const float4*)(g_Q + (size_t)s * HID))[lane];
        acc.x += fmaxf(p.x + q.x, 0.f);
        acc.y += fmaxf(p.y + q.y, 0.f);
        acc.z += fmaxf(p.z + q.z, 0.f);
        acc.w += fmaxf(p.w + q.w, 0.f);
    }
    int r = d & 127;
    uint32_t off = img_off(r, lane * 4);
    char* hB = (char*)g_sHi + (size_t)(d >> 7) * 32768;
    char* lB = (char*)g_sLo + (size_t)(d >> 7) * 32768;
    float hx = __bfloat162float(__float2bfloat16(acc.x));
    float hy = __bfloat162float(__float2bfloat16(acc.y));
    float hz = __bfloat162float(__float2bfloat16(acc.z));
    float hw = __bfloat162float(__float2bfloat16(acc.w));
    *(uint2*)(hB + off) = make_uint2(packbf(acc.x, acc.y), packbf(acc.z, acc.w));
    *(uint2*)(lB + off) = make_uint2(packbf(acc.x - hx, acc.y - hy),
                                     packbf(acc.z - hz, acc.w - hw));
}

// Serial overflow fixup (single warp; expected empty). RMW on S images.
__global__ void __launch_bounds__(32)
fixup_kernel()
{
    int total = g_novf;
    if (total > OVFMAX) total = OVFMAX;
    int lane = threadIdx.x;
    for (int j = 0; j < total; ++j) {
        int2 e = g_ovf[j];
        float4 p = ((const float4*)(g_P + (size_t)e.y * HID))[lane];
        float4 q = ((const float4*)(g_Q + (size_t)e.x * HID))[lane];
        int r = e.y & 127;
        uint32_t off = img_off(r, lane * 4);
        char* hB = (char*)g_sHi + (size_t)(e.y >> 7) * 32768;
        char* lB = (char*)g_sLo + (size_t)(e.y >> 7) * 32768;
        uint2 hh = *(uint2*)(hB + off);
        uint2 ll = *(uint2*)(lB + off);
        __nv_bfloat162 h0 = *(__nv_bfloat162*)&hh.x, h1 = *(__nv_bfloat162*)&hh.y;
        __nv_bfloat162 l0 = *(__nv_bfloat162*)&ll.x, l1 = *(__nv_bfloat162*)&ll.y;
        float vx = __bfloat162float(h0.x) + __bfloat162float(l0.x) + fmaxf(p.x + q.x, 0.f);
        float vy = __bfloat162float(h0.y) + __bfloat162float(l0.y) + fmaxf(p.y + q.y, 0.f);
        float vz = __bfloat162float(h1.x) + __bfloat162float(l1.x) + fmaxf(p.z + q.z, 0.f);
        float vw = __bfloat162float(h1.y) + __bfloat162float(l1.y) + fmaxf(p.w + q.w, 0.f);
        float hx = __bfloat162float(__float2bfloat16(vx));
        float hy = __bfloat162float(__float2bfloat16(vy));
        float hz = __bfloat162float(__float2bfloat16(vz));
        float hw = __bfloat162float(__float2bfloat16(vw));
        *(uint2*)(hB + off) = make_uint2(packbf(vx, vy), packbf(vz, vw));
        *(uint2*)(lB + off) = make_uint2(packbf(vx - hx, vy - hy),
                                         packbf(vz - hz, vw - hw));
        __syncwarp();
    }
}

__global__ void __launch_bounds__(256)
out_kernel(const float* __restrict__ H2, const float* __restrict__ Wc,
           const float* __restrict__ bc, float* __restrict__ out)
{
    int gw   = (blockIdx.x * blockDim.x + threadIdx.x) >> 5;
    int lane = threadIdx.x & 31;
    if (gw >= NODES) return;

    float4 hv  = ((const float4*)(H2 + (size_t)gw * HID))[lane];
    float4 w01 = ((const float4*)Wc)[lane * 2];
    float4 w23 = ((const float4*)Wc)[lane * 2 + 1];

    float a0 = hv.x * w01.x + hv.y * w01.z + hv.z * w23.x + hv.w * w23.z;
    float a1 = hv.x * w01.y + hv.y * w01.w + hv.z * w23.y + hv.w * w23.w;
#pragma unroll
    for (int off = 16; off > 0; off >>= 1) {
        a0 += __shfl_xor_sync(0xffffffffu, a0, off);
        a1 += __shfl_xor_sync(0xffffffffu, a1, off);
    }
    if (lane == 0) {
        out[(size_t)gw * 2]     = a0 + bc[0];
        out[(size_t)gw * 2 + 1] = a1 + bc[1];
    }
}

// ---------------------------------------------------------------------------
extern "C" void kernel_launch(void* const* d_in, const int* in_sizes, int n_in,
                              void* d_out, int out_size)
{
    const float* x    = (const float*)d_in[0];
    const int*   ei   = (const int*)d_in[1];
    const float* W_in = (const float*)d_in[2];
    const float* b_in = (const float*)d_in[3];
    const float* W1   = (const float*)d_in[4];
    const float* b1   = (const float*)d_in[5];
    const float* W2   = (const float*)d_in[6];
    const float* b2   = (const float*)d_in[7];
    const float* Wc   = (const float*)d_in[8];
    const float* bc   = (const float*)d_in[9];
    float*       out  = (float*)d_out;

    void *ph2, *pP, *pQ, *pcnt, *pWin, *pW1a, *pW1b, *pW2, *psHi, *psLo;
    cudaGetSymbolAddress(&ph2,  g_h2);
    cudaGetSymbolAddress(&pP,   g_P);
    cudaGetSymbolAddress(&pQ,   g_Q);
    cudaGetSymbolAddress(&pcnt, g_cnt);
    cudaGetSymbolAddress(&pWin, g_iWin);
    cudaGetSymbolAddress(&pW1a, g_iW1a);
    cudaGetSymbolAddress(&pW1b, g_iW1b);
    cudaGetSymbolAddress(&pW2,  g_iW2);
    cudaGetSymbolAddress(&psHi, g_sHi);
    cudaGetSymbolAddress(&psLo, g_sLo);

    cudaFuncSetAttribute(gemm_hpq, cudaFuncAttributeMaxDynamicSharedMemorySize,
                         224 * 1024);
    cudaFuncSetAttribute(gemm_b, cudaFuncAttributeMaxDynamicSharedMemorySize,
                         192 * 1024);

    const int M = NODES;
    const int GRID = 148;

    prep_kernel<<<256, 256>>>(W_in, W1, W2);
    zero_kernel<<<256, 256>>>();
    bucket_kernel<<<(EDGES + 255) / 256, 256>>>(ei);

    // 1) fused: h (smem-only) from x@Win; P = h@W1a + b1; Q = h@W1b
    gemm_hpq<<<GRID, 512, 224 * 1024>>>(x, (const uint4*)pWin,
                                        (const uint4*)pW1a, (const uint4*)pW1b,
                                        b_in, b1, (float*)pP, (float*)pQ,
                                        M, NTILES);
    // 2) S images = split( sum_e relu(P[d]+Q[s]) )
    node_kernel<<<(NODES * 32 + 255) / 256, 256>>>();
    fixup_kernel<<<1, 32>>>();
    // 3) h2 = relu(S @ W2 + deg*b2)
    gemm_b<<<GRID, 512, 192 * 1024>>>((const uint4*)psHi, (const uint4*)psLo,
                                      (const uint4*)pW2, b2, (const int*)pcnt,
                                      (float*)ph2, M, NTILES, 1);
    // 4) out = h2 @ Wc + bc
    out_kernel<<<(NODES * 32 + 255) / 256, 256>>>((const float*)ph2, Wc, bc, out);
}

// round 12
// speedup vs baseline: 1.3647x; 1.3647x over previous
#include <cuda_runtime.h>
#include <cuda_bf16.h>
#include <cstdint>

#define NODES 50000
#define EDGES 800000
#define HID   128
#define CAP   128
#define OVFMAX 65536
#define NTILES 391            // ceil(50000/128)

// ---------------------------------------------------------------------------
// Device-global scratch (no allocations allowed)
// ---------------------------------------------------------------------------
__device__ float g_h2[(size_t)NODES * HID];
__device__ float g_P[(size_t)NODES * HID];
__device__ float g_Q[(size_t)NODES * HID];
__device__ int   g_cnt[NODES];
__device__ int   g_bucket[(size_t)NODES * CAP];
__device__ int2  g_ovf[OVFMAX];
__device__ int   g_novf;

// bf16 hi/lo "image" arrays: per 128-row tile, 32 KB contiguous, element (r,k)
// at byte off = r*256 + ((k>>6)<<7) + (((k&63)<<1) ^ ((r&7)<<4)).
__device__ uint4 g_hHi[(size_t)NTILES * 2048];
__device__ uint4 g_hLo[(size_t)NTILES * 2048];
__device__ uint4 g_sHi[(size_t)NTILES * 2048];
__device__ uint4 g_sLo[(size_t)NTILES * 2048];

// Weight images (transposed, hi block 32KB then lo block 32KB)
__device__ uint4 g_iWin[4096];
__device__ uint4 g_iW1a[4096];
__device__ uint4 g_iW1b[4096];
__device__ uint4 g_iW2 [4096];

// ---------------------------------------------------------------------------
__device__ __forceinline__ uint32_t smem_u32(const void* p) {
    uint32_t a;
    asm("{ .reg .u64 t; cvta.to.shared.u64 t, %1; cvt.u32.u64 %0, t; }"
        : "=r"(a) : "l"(p));
    return a;
}
__device__ __forceinline__ unsigned packbf(float x, float y) {
    __nv_bfloat162 t = __floats2bfloat162_rn(x, y);
    return *reinterpret_cast<unsigned*>(&t);
}
__device__ __forceinline__ void ldsm4(unsigned* r, uint32_t addr) {
    asm volatile("ldmatrix.sync.aligned.m8n8.x4.shared.b16 {%0,%1,%2,%3}, [%4];"
                 : "=r"(r[0]), "=r"(r[1]), "=r"(r[2]), "=r"(r[3]) : "r"(addr));
}
__device__ __forceinline__ void mma16816(float* d, const unsigned* a,
                                         unsigned b0, unsigned b1) {
    asm volatile(
        "mma.sync.aligned.m16n8k16.row.col.f32.bf16.bf16.f32 "
        "{%0,%1,%2,%3},{%4,%5,%6,%7},{%8,%9},{%0,%1,%2,%3};"
        : "+f"(d[0]), "+f"(d[1]), "+f"(d[2]), "+f"(d[3])
        : "r"(a[0]), "r"(a[1]), "r"(a[2]), "r"(a[3]), "r"(b0), "r"(b1));
}
__device__ __forceinline__ void cpa16(uint32_t dst, const void* src) {
    asm volatile("cp.async.cg.shared.global [%0], [%1], 16;"
                 :: "r"(dst), "l"(src));
}
__device__ __forceinline__ void cpa16z(uint32_t dst, const void* src, int sz) {
    asm volatile("cp.async.cg.shared.global [%0], [%1], 16, %2;"
                 :: "r"(dst), "l"(src), "r"(sz));
}
#define CP_COMMIT() asm volatile("cp.async.commit_group;" ::: "memory")
#define CP_WAIT0()  asm volatile("cp.async.wait_group 0;" ::: "memory")

__device__ __forceinline__ uint32_t img_off(int r, int k) {
    return (uint32_t)r * 256 + ((k >> 6) << 7) + ((((k & 63) << 1)) ^ ((r & 7) << 4));
}
__device__ __forceinline__ uint32_t f32_off(int r, int cc) {
    return (uint32_t)r * 512 +
           (((uint32_t)cc * 16) ^ ((r & 7) << 4) ^ ((cc >> 3) << 4));
}

// ---------------------------------------------------------------------------
// Prep: weight images
// ---------------------------------------------------------------------------
__device__ __forceinline__ void img_write(uint4* img, int n, int k, float v) {
    __nv_bfloat16 hi = __float2bfloat16(v);
    float hf = __bfloat162float(hi);
    __nv_bfloat16 lo = __float2bfloat16(v - hf);
    uint32_t off = img_off(n, k);
    __nv_bfloat16* p = (__nv_bfloat16*)img;
    p[off >> 1]               = hi;
    p[128 * 128 + (off >> 1)] = lo;
}

__global__ void __launch_bounds__(256)
prep_kernel(const float* __restrict__ W_in, const float* __restrict__ W1,
            const float* __restrict__ W2)
{
    int idx = blockIdx.x * blockDim.x + threadIdx.x;
    int n = (idx >> 7) & 127, k = idx & 127;
    if (idx < 16384) {
        img_write(g_iWin, n, k, W_in[k * 128 + n]);
    } else if (idx < 32768) {
        img_write(g_iW1a, n, k, W1[k * 128 + n]);
    } else if (idx < 49152) {
        img_write(g_iW1b, n, k, W1[(128 + k) * 128 + n]);
    } else if (idx < 65536) {
        img_write(g_iW2, n, k, W2[k * 128 + n]);
    }
}

// ---------------------------------------------------------------------------
// Mainloop with frag reuse: per k-step load Ah/Al/Bh/Bl frags once (8 ldsm4),
// issue 24 HMMAs (AhBh + AlBh + AhBl).
// ---------------------------------------------------------------------------
__device__ __forceinline__ void tile_mainloop(
    float acc[2][4][4], uint32_t aHi, uint32_t aLo, uint32_t bHi, uint32_t bLo,
    int warpM, int warpN, int fi, int fswz, int fk8)
{
#pragma unroll
    for (int mt = 0; mt < 2; ++mt)
#pragma unroll
        for (int ns = 0; ns < 4; ++ns)
#pragma unroll
            for (int e = 0; e < 4; ++e) acc[mt][ns][e] = 0.f;

#pragma unroll
    for (int ks = 0; ks < 8; ++ks) {
        const int k8 = ks * 16 + fk8;
        const uint32_t koff = ((k8 >> 6) << 7) + (((k8 & 63) << 1) ^ fswz);
        unsigned ah[2][4], al[2][4], bh[2][4], bl[2][4];
#pragma unroll
        for (int mt = 0; mt < 2; ++mt) {
            uint32_t ra = (uint32_t)(warpM * 32 + mt * 16 + fi) * 256 + koff;
            ldsm4(ah[mt], aHi + ra);
            ldsm4(al[mt], aLo + ra);
        }
#pragma unroll
        for (int nt = 0; nt < 2; ++nt) {
            uint32_t rb = (uint32_t)(warpN * 32 + nt * 16 + fi) * 256 + koff;
            ldsm4(bh[nt], bHi + rb);
            ldsm4(bl[nt], bLo + rb);
        }
#pragma unroll
        for (int mt = 0; mt < 2; ++mt)
#pragma unroll
            for (int nt = 0; nt < 2; ++nt) {
                mma16816(acc[mt][nt * 2],     ah[mt], bh[nt][0], bh[nt][2]);
                mma16816(acc[mt][nt * 2 + 1], ah[mt], bh[nt][1], bh[nt][3]);
                mma16816(acc[mt][nt * 2],     al[mt], bh[nt][0], bh[nt][2]);
                mma16816(acc[mt][nt * 2 + 1], al[mt], bh[nt][1], bh[nt][3]);
                mma16816(acc[mt][nt * 2],     ah[mt], bl[nt][0], bl[nt][2]);
                mma16816(acc[mt][nt * 2 + 1], ah[mt], bl[nt][1], bl[nt][3]);
            }
    }
}

// fp32 epilogue (optional rowcnt-scaled bias + relu)
__device__ __forceinline__ void epi_f32(
    float acc[2][4][4], float* __restrict__ C, const float* __restrict__ bias,
    const int* __restrict__ rowcnt, int m0, int M, int do_relu,
    int warpM, int warpN, int L)
{
#pragma unroll
    for (int mt = 0; mt < 2; ++mt) {
        int gr0 = m0 + warpM * 32 + mt * 16 + (L >> 2);
        int gr1 = gr0 + 8;
        float sc0 = 1.f, sc1 = 1.f;
        if (rowcnt) {
            if (gr0 < M) sc0 = (float)rowcnt[gr0];
            if (gr1 < M) sc1 = (float)rowcnt[gr1];
        }
#pragma unroll
        for (int ns = 0; ns < 4; ++ns) {
            int c = warpN * 32 + ns * 8 + (L & 3) * 2;
            float b0 = bias ? bias[c]     : 0.f;
            float b1 = bias ? bias[c + 1] : 0.f;
            float v00 = acc[mt][ns][0] + sc0 * b0;
            float v01 = acc[mt][ns][1] + sc0 * b1;
            float v10 = acc[mt][ns][2] + sc1 * b0;
            float v11 = acc[mt][ns][3] + sc1 * b1;
            if (do_relu) {
                v00 = fmaxf(v00, 0.f); v01 = fmaxf(v01, 0.f);
                v10 = fmaxf(v10, 0.f); v11 = fmaxf(v11, 0.f);
            }
            if (gr0 < M) *(float2*)(C + (size_t)gr0 * 128 + c) = make_float2(v00, v01);
            if (gr1 < M) *(float2*)(C + (size_t)gr1 * 128 + c) = make_float2(v10, v11);
        }
    }
}

// ---------------------------------------------------------------------------
// gemm_xa: fp32 A input via double-buffered cp.async; in-smem convert to
// hi/lo images (in place); mainloop; epilogue -> relu+bias, hi/lo images.
// smem: [A0 64K][A1 64K][W 64K] = 192 KB.
// ---------------------------------------------------------------------------
__global__ void __launch_bounds__(512, 1)
gemm_xa(const float* __restrict__ A, const uint4* __restrict__ Wimg,
        const float* __restrict__ bias, uint4* __restrict__ outHi,
        uint4* __restrict__ outLo, int M, int ntiles)
{
    extern __shared__ char smem[];
    const uint32_t sb = smem_u32(smem);
    const uint32_t sW = sb + 131072;

    const int tid = threadIdx.x;
    const int wid = tid >> 5;
    const int L   = tid & 31;
    const int warpM = wid >> 2, warpN = wid & 3;
    const int fi = L & 15, fswz = (fi & 7) << 4, fk8 = (L >> 4) * 8;
    const int sr = tid >> 2, sq = tid & 3;   // convert mapping: 4 thr/row

    for (int i = tid; i < 4096; i += 512) cpa16(sW + i * 16, Wimg + i);
    // prologue: fp32 copy of first tile (swizzled, zero-padded)
    {
        int m0 = blockIdx.x * 128;
        for (int i = tid; i < 4096; i += 512) {
            int r = i >> 5, cc = i & 31;
            int gr = m0 + r;
            int sz = (gr < M) ? 16 : 0;
            const float* src = A + (size_t)(gr < M ? gr : 0) * 128 + cc * 4;
            cpa16z(sb + f32_off(r, cc), src, sz);
        }
    }
    CP_COMMIT();

    int cur = 0;
    for (int tile = blockIdx.x; tile < ntiles; tile += gridDim.x) {
        CP_WAIT0();
        __syncthreads();

        const uint32_t sA = sb + cur * 65536;

        // read fp32 (conflict-free swizzled) into regs
        float4 v[8];
#pragma unroll
        for (int j = 0; j < 8; ++j)
            v[j] = *(const float4*)(smem + cur * 65536 +
                                    f32_off(sr, sq * 8 + j));

        // prefetch next tile's fp32 into the other buffer
        int nxt = tile + gridDim.x;
        if (nxt < ntiles) {
            uint32_t dst = sb + (cur ^ 1) * 65536;
            int m0n = nxt * 128;
            for (int i = tid; i < 4096; i += 512) {
                int r = i >> 5, cc = i & 31;
                int gr = m0n + r;
                int sz = (gr < M) ? 16 : 0;
                const float* src = A + (size_t)(gr < M ? gr : 0) * 128 + cc * 4;
                cpa16z(dst + f32_off(r, cc), src, sz);
            }
        }
        CP_COMMIT();
        __syncthreads();   // all fp32 reads of cur done

        // in-place convert: write hi (0..32K) / lo (32..64K) images
#pragma unroll
        for (int j = 0; j < 8; ++j) {
            float4 a = v[j];
            float hx = __bfloat162float(__float2bfloat16(a.x));
            float hy = __bfloat162float(__float2bfloat16(a.y));
            float hz = __bfloat162float(__float2bfloat16(a.z));
            float hw = __bfloat162float(__float2bfloat16(a.w));
            uint32_t off = img_off(sr, (sq * 8 + j) * 4);
            *(uint2*)(smem + cur * 65536 + off) =
                make_uint2(packbf(a.x, a.y), packbf(a.z, a.w));
            *(uint2*)(smem + cur * 65536 + 32768 + off) =
                make_uint2(packbf(a.x - hx, a.y - hy), packbf(a.z - hz, a.w - hw));
        }
        __syncthreads();

        float acc[2][4][4];
        tile_mainloop(acc, sA, sA + 32768, sW, sW + 32768,
                      warpM, warpN, fi, fswz, fk8);

        // epilogue: relu+bias, split, write hi/lo images
        const int m0 = tile * 128;
        char* hB = (char*)outHi + (size_t)tile * 32768;
        char* lB = (char*)outLo + (size_t)tile * 32768;
#pragma unroll
        for (int mt = 0; mt < 2; ++mt) {
            int r0 = warpM * 32 + mt * 16 + (L >> 2);
            int r1 = r0 + 8;
#pragma unroll
            for (int ns = 0; ns < 4; ++ns) {
                int c = warpN * 32 + ns * 8 + (L & 3) * 2;
                float b0 = bias[c], b1 = bias[c + 1];
                float v00 = fmaxf(acc[mt][ns][0] + b0, 0.f);
                float v01 = fmaxf(acc[mt][ns][1] + b1, 0.f);
                float v10 = fmaxf(acc[mt][ns][2] + b0, 0.f);
                float v11 = fmaxf(acc[mt][ns][3] + b1, 0.f);
                if (m0 + r0 < M) {
                    uint32_t off = img_off(r0, c);
                    float h0 = __bfloat162float(__float2bfloat16(v00));
                    float h1 = __bfloat162float(__float2bfloat16(v01));
                    *(unsigned*)(hB + off) = packbf(v00, v01);
                    *(unsigned*)(lB + off) = packbf(v00 - h0, v01 - h1);
                }
                if (m0 + r1 < M) {
                    uint32_t off = img_off(r1, c);
                    float h0 = __bfloat162float(__float2bfloat16(v10));
                    float h1 = __bfloat162float(__float2bfloat16(v11));
                    *(unsigned*)(hB + off) = packbf(v10, v11);
                    *(unsigned*)(lB + off) = packbf(v10 - h0, v11 - h1);
                }
            }
        }
        cur ^= 1;
    }
}

// ---------------------------------------------------------------------------
// gemm_b: image input, cp.async double-buffered; fp32 output.
// smem: [A0 64K][A1 64K][W 64K] = 192 KB.
// ---------------------------------------------------------------------------
__global__ void __launch_bounds__(512, 1)
gemm_b(const uint4* __restrict__ hiImg, const uint4* __restrict__ loImg,
       const uint4* __restrict__ Wimg, const float* __restrict__ bias,
       const int* __restrict__ rowcnt, float* __restrict__ C,
       int M, int ntiles, int do_relu)
{
    extern __shared__ char smem[];
    const uint32_t sb = smem_u32(smem);
    const uint32_t sW = sb + 131072;

    const int tid = threadIdx.x;
    const int wid = tid >> 5;
    const int L   = tid & 31;
    const int warpM = wid >> 2, warpN = wid & 3;
    const int fi = L & 15, fswz = (fi & 7) << 4, fk8 = (L >> 4) * 8;

    for (int i = tid; i < 4096; i += 512) cpa16(sW + i * 16, Wimg + i);
    {
        int t0 = blockIdx.x;
        if (t0 < ntiles) {
            const uint4* sH = hiImg + (size_t)t0 * 2048;
            const uint4* sL = loImg + (size_t)t0 * 2048;
            for (int i = tid; i < 2048; i += 512) {
                cpa16(sb + i * 16, sH + i);
                cpa16(sb + 32768 + i * 16, sL + i);
            }
        }
    }
    CP_COMMIT();

    int cur = 0;
    for (int tile = blockIdx.x; tile < ntiles; tile += gridDim.x) {
        CP_WAIT0();
        __syncthreads();

        int nxt = tile + gridDim.x;
        if (nxt < ntiles) {
            uint32_t dst = sb + (cur ^ 1) * 65536;
            const uint4* sH = hiImg + (size_t)nxt * 2048;
            const uint4* sL = loImg + (size_t)nxt * 2048;
            for (int i = tid; i < 2048; i += 512) {
                cpa16(dst + i * 16, sH + i);
                cpa16(dst + 32768 + i * 16, sL + i);
            }
        }
        CP_COMMIT();

        const uint32_t sAh = sb + cur * 65536;
        float acc[2][4][4];
        tile_mainloop(acc, sAh, sAh + 32768, sW, sW + 32768,
                      warpM, warpN, fi, fswz, fk8);

        epi_f32(acc, C, bias, rowcnt, tile * 128, M, do_relu, warpM, warpN, L);
        cur ^= 1;
    }
}

// ---------------------------------------------------------------------------
// gemm_pq2: split grid. CTAs [0,74) compute P (W1a, +b1); [74,148) compute Q.
// Double-buffered like gemm_b.
// ---------------------------------------------------------------------------
__global__ void __launch_bounds__(512, 1)
gemm_pq2(const uint4* __restrict__ hiImg, const uint4* __restrict__ loImg,
         const uint4* __restrict__ Wa, const uint4* __restrict__ Wb,
         const float* __restrict__ b1, float* __restrict__ P,
         float* __restrict__ Q, int M, int ntiles)
{
    extern __shared__ char smem[];
    const uint32_t sb = smem_u32(smem);
    const uint32_t sW = sb + 131072;

    const int half = (blockIdx.x >= 74) ? 1 : 0;
    const int base = blockIdx.x - half * 74;
    const uint4* Wimg = half ? Wb : Wa;
    float* C = half ? Q : P;
    const float* bias = half ? nullptr : b1;

    const int tid = threadIdx.x;
    const int wid = tid >> 5;
    const int L   = tid & 31;
    const int warpM = wid >> 2, warpN = wid & 3;
    const int fi = L & 15, fswz = (fi & 7) << 4, fk8 = (L >> 4) * 8;

    for (int i = tid; i < 4096; i += 512) cpa16(sW + i * 16, Wimg + i);
    {
        const uint4* sH = hiImg + (size_t)base * 2048;
        const uint4* sL = loImg + (size_t)base * 2048;
        for (int i = tid; i < 2048; i += 512) {
            cpa16(sb + i * 16, sH + i);
            cpa16(sb + 32768 + i * 16, sL + i);
        }
    }
    CP_COMMIT();

    int cur = 0;
    for (int tile = base; tile < ntiles; tile += 74) {
        CP_WAIT0();
        __syncthreads();

        int nxt = tile + 74;
        if (nxt < ntiles) {
            uint32_t dst = sb + (cur ^ 1) * 65536;
            const uint4* sH = hiImg + (size_t)nxt * 2048;
            const uint4* sL = loImg + (size_t)nxt * 2048;
            for (int i = tid; i < 2048; i += 512) {
                cpa16(dst + i * 16, sH + i);
                cpa16(dst + 32768 + i * 16, sL + i);
            }
        }
        CP_COMMIT();

        const uint32_t sAh = sb + cur * 65536;
        float acc[2][4][4];
        tile_mainloop(acc, sAh, sAh + 32768, sW, sW + 32768,
                      warpM, warpN, fi, fswz, fk8);

        epi_f32(acc, C, bias, nullptr, tile * 128, M, 0, warpM, warpN, L);
        cur ^= 1;
    }
}

// ---------------------------------------------------------------------------
__global__ void __launch_bounds__(256)
zero_kernel()
{
    int idx = blockIdx.x * blockDim.x + threadIdx.x;
    int stride = gridDim.x * blockDim.x;
    for (int i = idx; i < NODES; i += stride) g_cnt[i] = 0;
    if (idx == 0) g_novf = 0;
}

__global__ void __launch_bounds__(256)
bucket_kernel(const int* __restrict__ ei)
{
    int e = blockIdx.x * blockDim.x + threadIdx.x;
    if (e >= EDGES) return;
    int s = ei[e];
    int d = ei[EDGES + e];
    int slot = atomicAdd(&g_cnt[d], 1);
    if (slot < CAP) {
        g_bucket[(size_t)d * CAP + slot] = s;
    } else {
        int o = atomicAdd(&g_novf, 1);
        if (o < OVFMAX) g_ovf[o] = make_int2(s, d);
    }
}

// Warp per node: S[d] = sum relu(P[d]+Q[src]); write S as bf16 hi/lo images.
__global__ void __launch_bounds__(256)
node_kernel()
{
    int d    = (blockIdx.x * blockDim.x + threadIdx.x) >> 5;
    int lane = threadIdx.x & 31;
    if (d >= NODES) return;

    int n = g_cnt[d];
    if (n > CAP) n = CAP;

    float4 p = ((const float4*)(g_P + (size_t)d * HID))[lane];
    float4 acc = make_float4(0.f, 0.f, 0.f, 0.f);
    const int* bkt = g_bucket + (size_t)d * CAP;
#pragma unroll 2
    for (int i = 0; i < n; ++i) {
        int s = __ldg(bkt + i);
        float4 q = ((const float4*)(g_Q + (size_t)s * HID))[lane];
        acc.x += fmaxf(p.x + q.x, 0.f);
        acc.y += fmaxf(p.y + q.y, 0.f);
        acc.z += fmaxf(p.z + q.z, 0.f);
        acc.w += fmaxf(p.w + q.w, 0.f);
    }
    int r = d & 127;
    uint32_t off = img_off(r, lane * 4);
    char* hB = (char*)g_sHi + (size_t)(d >> 7) * 32768;
    char* lB = (char*)g_sLo + (size_t)(d >> 7) * 32768;
    float hx = __bfloat162float(__float2bfloat16(acc.x));
    float hy = __bfloat162float(__float2bfloat16(acc.y));
    float hz = __bfloat162float(__float2bfloat16(acc.z));
    float hw = __bfloat162float(__float2bfloat16(acc.w));
    *(uint2*)(hB + off) = make_uint2(packbf(acc.x, acc.y), packbf(acc.z, acc.w));
    *(uint2*)(lB + off) = make_uint2(packbf(acc.x - hx, acc.y - hy),
                                     packbf(acc.z - hz, acc.w - hw));
}

// Serial overflow fixup (single warp; expected empty). RMW on S images.
__global__ void __launch_bounds__(32)
fixup_kernel()
{
    int total = g_novf;
    if (total > OVFMAX) total = OVFMAX;
    int lane = threadIdx.x;
    for (int j = 0; j < total; ++j) {
        int2 e = g_ovf[j];
        float4 p = ((const float4*)(g_P + (size_t)e.y * HID))[lane];
        float4 q = ((const float4*)(g_Q + (size_t)e.x * HID))[lane];
        int r = e.y & 127;
        uint32_t off = img_off(r, lane * 4);
        char* hB = (char*)g_sHi + (size_t)(e.y >> 7) * 32768;
        char* lB = (char*)g_sLo + (size_t)(e.y >> 7) * 32768;
        uint2 hh = *(uint2*)(hB + off);
        uint2 ll = *(uint2*)(lB + off);
        __nv_bfloat162 h0 = *(__nv_bfloat162*)&hh.x, h1 = *(__nv_bfloat162*)&hh.y;
        __nv_bfloat162 l0 = *(__nv_bfloat162*)&ll.x, l1 = *(__nv_bfloat162*)&ll.y;
        float vx = __bfloat162float(h0.x) + __bfloat162float(l0.x) + fmaxf(p.x + q.x, 0.f);
        float vy = __bfloat162float(h0.y) + __bfloat162float(l0.y) + fmaxf(p.y + q.y, 0.f);
        float vz = __bfloat162float(h1.x) + __bfloat162float(l1.x) + fmaxf(p.z + q.z, 0.f);
        float vw = __bfloat162float(h1.y) + __bfloat162float(l1.y) + fmaxf(p.w + q.w, 0.f);
        float hx = __bfloat162float(__float2bfloat16(vx));
        float hy = __bfloat162float(__float2bfloat16(vy));
        float hz = __bfloat162float(__float2bfloat16(vz));
        float hw = __bfloat162float(__float2bfloat16(vw));
        *(uint2*)(hB + off) = make_uint2(packbf(vx, vy), packbf(vz, vw));
        *(uint2*)(lB + off) = make_uint2(packbf(vx - hx, vy - hy),
                                         packbf(vz - hz, vw - hw));
        __syncwarp();
    }
}

__global__ void __launch_bounds__(256)
out_kernel(const float* __restrict__ H2, const float* __restrict__ Wc,
           const float* __restrict__ bc, float* __restrict__ out)
{
    int gw   = (blockIdx.x * blockDim.x + threadIdx.x) >> 5;
    int lane = threadIdx.x & 31;
    if (gw >= NODES) return;

    float4 hv  = ((const float4*)(H2 + (size_t)gw * HID))[lane];
    float4 w01 = ((const float4*)Wc)[lane * 2];
    float4 w23 = ((const float4*)Wc)[lane * 2 + 1];

    float a0 = hv.x * w01.x + hv.y * w01.z + hv.z * w23.x + hv.w * w23.z;
    float a1 = hv.x * w01.y + hv.y * w01.w + hv.z * w23.y + hv.w * w23.w;
#pragma unroll
    for (int off = 16; off > 0; off >>= 1) {
        a0 += __shfl_xor_sync(0xffffffffu, a0, off);
        a1 += __shfl_xor_sync(0xffffffffu, a1, off);
    }
    if (lane == 0) {
        out[(size_t)gw * 2]     = a0 + bc[0];
        out[(size_t)gw * 2 + 1] = a1 + bc[1];
    }
}

// ---------------------------------------------------------------------------
extern "C" void kernel_launch(void* const* d_in, const int* in_sizes, int n_in,
                              void* d_out, int out_size)
{
    const float* x    = (const float*)d_in[0];
    const int*   ei   = (const int*)d_in[1];
    const float* W_in = (const float*)d_in[2];
    const float* b_in = (const float*)d_in[3];
    const float* W1   = (const float*)d_in[4];
    const float* b1   = (const float*)d_in[5];
    const float* W2   = (const float*)d_in[6];
    const float* b2   = (const float*)d_in[7];
    const float* Wc   = (const float*)d_in[8];
    const float* bc   = (const float*)d_in[9];
    float*       out  = (float*)d_out;

    void *ph2, *pP, *pQ, *pcnt, *pWin, *pW1a, *pW1b, *pW2;
    void *phHi, *phLo, *psHi, *psLo;
    cudaGetSymbolAddress(&ph2,  g_h2);
    cudaGetSymbolAddress(&pP,   g_P);
    cudaGetSymbolAddress(&pQ,   g_Q);
    cudaGetSymbolAddress(&pcnt, g_cnt);
    cudaGetSymbolAddress(&pWin, g_iWin);
    cudaGetSymbolAddress(&pW1a, g_iW1a);
    cudaGetSymbolAddress(&pW1b, g_iW1b);
    cudaGetSymbolAddress(&pW2,  g_iW2);
    cudaGetSymbolAddress(&phHi, g_hHi);
    cudaGetSymbolAddress(&phLo, g_hLo);
    cudaGetSymbolAddress(&psHi, g_sHi);
    cudaGetSymbolAddress(&psLo, g_sLo);

    cudaFuncSetAttribute(gemm_xa, cudaFuncAttributeMaxDynamicSharedMemorySize,
                         192 * 1024);
    cudaFuncSetAttribute(gemm_b, cudaFuncAttributeMaxDynamicSharedMemorySize,
                         192 * 1024);
    cudaFuncSetAttribute(gemm_pq2, cudaFuncAttributeMaxDynamicSharedMemorySize,
                         192 * 1024);

    const int M = NODES;
    const int GRID = 148;

    prep_kernel<<<256, 256>>>(W_in, W1, W2);
    zero_kernel<<<256, 256>>>();
    bucket_kernel<<<(EDGES + 255) / 256, 256>>>(ei);

    // 1) h images = split(relu(x @ Win + b_in)), pipelined fp32->image convert
    gemm_xa<<<GRID, 512, 192 * 1024>>>(x, (const uint4*)pWin, b_in,
                                       (uint4*)phHi, (uint4*)phLo, M, NTILES);
    // 2+3) P = h @ W1a + b1 ; Q = h @ W1b (split-grid fused)
    gemm_pq2<<<GRID, 512, 192 * 1024>>>((const uint4*)phHi, (const uint4*)phLo,
                                        (const uint4*)pW1a, (const uint4*)pW1b,
                                        b1, (float*)pP, (float*)pQ, M, NTILES);
    // 4) S images = split( sum_e relu(P[d]+Q[s]) )
    node_kernel<<<(NODES * 32 + 255) / 256, 256>>>();
    fixup_kernel<<<1, 32>>>();
    // 5) h2 = relu(S @ W2 + deg*b2)
    gemm_b<<<GRID, 512, 192 * 1024>>>((const uint4*)psHi, (const uint4*)psLo,
                                      (const uint4*)pW2, b2, (const int*)pcnt,
                                      (float*)ph2, M, NTILES, 1);
    // 6) out = h2 @ Wc + bc
    out_kernel<<<(NODES * 32 + 255) / 256, 256>>>((const float*)ph2, Wc, bc, out);
}

// round 13
// speedup vs baseline: 1.4041x; 1.0289x over previous
#include <cuda_runtime.h>
#include <cuda_bf16.h>
#include <cstdint>

#define NODES 50000
#define EDGES 800000
#define HID   128
#define CAP   128
#define OVFMAX 65536
#define NTILES  391           // ceil(50000/128)  (gmem image blocks)
#define NT64    782           // ceil(50000/64)   (GEMM tiles)

// ---------------------------------------------------------------------------
// Device-global scratch (no allocations allowed)
// ---------------------------------------------------------------------------
__device__ float g_h2[(size_t)NODES * HID];
__device__ float g_P[(size_t)NODES * HID];
__device__ float g_Q[(size_t)NODES * HID];
__device__ int   g_cnt[NODES];
__device__ int   g_bucket[(size_t)NODES * CAP];
__device__ int2  g_ovf[OVFMAX];
__device__ int   g_novf;

// bf16 hi/lo "image" arrays: per 128-row block, 32 KB contiguous, element (r,k)
// at byte off = r*256 + ((k>>6)<<7) + (((k&63)<<1) ^ ((r&7)<<4)).
__device__ uint4 g_hHi[(size_t)NTILES * 2048];
__device__ uint4 g_hLo[(size_t)NTILES * 2048];
__device__ uint4 g_sHi[(size_t)NTILES * 2048];
__device__ uint4 g_sLo[(size_t)NTILES * 2048];

// Weight images (transposed, hi block 32KB then lo block 32KB)
__device__ uint4 g_iWin[4096];
__device__ uint4 g_iW1a[4096];
__device__ uint4 g_iW1b[4096];
__device__ uint4 g_iW2 [4096];

// ---------------------------------------------------------------------------
__device__ __forceinline__ uint32_t smem_u32(const void* p) {
    uint32_t a;
    asm("{ .reg .u64 t; cvta.to.shared.u64 t, %1; cvt.u32.u64 %0, t; }"
        : "=r"(a) : "l"(p));
    return a;
}
__device__ __forceinline__ unsigned packbf(float x, float y) {
    __nv_bfloat162 t = __floats2bfloat162_rn(x, y);
    return *reinterpret_cast<unsigned*>(&t);
}
__device__ __forceinline__ void ldsm4(unsigned* r, uint32_t addr) {
    asm volatile("ldmatrix.sync.aligned.m8n8.x4.shared.b16 {%0,%1,%2,%3}, [%4];"
                 : "=r"(r[0]), "=r"(r[1]), "=r"(r[2]), "=r"(r[3]) : "r"(addr));
}
__device__ __forceinline__ void mma16816(float* d, const unsigned* a,
                                         unsigned b0, unsigned b1) {
    asm volatile(
        "mma.sync.aligned.m16n8k16.row.col.f32.bf16.bf16.f32 "
        "{%0,%1,%2,%3},{%4,%5,%6,%7},{%8,%9},{%0,%1,%2,%3};"
        : "+f"(d[0]), "+f"(d[1]), "+f"(d[2]), "+f"(d[3])
        : "r"(a[0]), "r"(a[1]), "r"(a[2]), "r"(a[3]), "r"(b0), "r"(b1));
}
__device__ __forceinline__ void cpa16(uint32_t dst, const void* src) {
    asm volatile("cp.async.cg.shared.global [%0], [%1], 16;"
                 :: "r"(dst), "l"(src));
}
__device__ __forceinline__ void cpa16z(uint32_t dst, const void* src, int sz) {
    asm volatile("cp.async.cg.shared.global [%0], [%1], 16, %2;"
                 :: "r"(dst), "l"(src), "r"(sz));
}
#define CP_COMMIT() asm volatile("cp.async.commit_group;" ::: "memory")
#define CP_WAIT0()  asm volatile("cp.async.wait_group 0;" ::: "memory")

__device__ __forceinline__ uint32_t img_off(int r, int k) {
    return (uint32_t)r * 256 + ((k >> 6) << 7) + ((((k & 63) << 1)) ^ ((r & 7) << 4));
}
__device__ __forceinline__ uint32_t f32_off(int r, int cc) {
    return (uint32_t)r * 512 +
           (((uint32_t)cc * 16) ^ ((r & 7) << 4) ^ ((cc >> 3) << 4));
}

// ---------------------------------------------------------------------------
// Prep: weight images
// ---------------------------------------------------------------------------
__device__ __forceinline__ void img_write(uint4* img, int n, int k, float v) {
    __nv_bfloat16 hi = __float2bfloat16(v);
    float hf = __bfloat162float(hi);
    __nv_bfloat16 lo = __float2bfloat16(v - hf);
    uint32_t off = img_off(n, k);
    __nv_bfloat16* p = (__nv_bfloat16*)img;
    p[off >> 1]               = hi;
    p[128 * 128 + (off >> 1)] = lo;
}

__global__ void __launch_bounds__(256)
prep_kernel(const float* __restrict__ W_in, const float* __restrict__ W1,
            const float* __restrict__ W2)
{
    int idx = blockIdx.x * blockDim.x + threadIdx.x;
    int n = (idx >> 7) & 127, k = idx & 127;
    if (idx < 16384) {
        img_write(g_iWin, n, k, W_in[k * 128 + n]);
    } else if (idx < 32768) {
        img_write(g_iW1a, n, k, W1[k * 128 + n]);
    } else if (idx < 49152) {
        img_write(g_iW1b, n, k, W1[(128 + k) * 128 + n]);
    } else if (idx < 65536) {
        img_write(g_iW2, n, k, W2[k * 128 + n]);
    }
}

// ---------------------------------------------------------------------------
// Mainloop (64-row A tile): per k-step load Ah/Al/Bh/Bl frags once (8 ldsm4),
// issue 24 HMMAs (AhBh + AlBh + AhBl). Warp tile 32x32; 8 warps = 64x128.
// ---------------------------------------------------------------------------
__device__ __forceinline__ void tile_mainloop(
    float acc[2][4][4], uint32_t aHi, uint32_t aLo, uint32_t bHi, uint32_t bLo,
    int warpM, int warpN, int fi, int fswz, int fk8)
{
#pragma unroll
    for (int mt = 0; mt < 2; ++mt)
#pragma unroll
        for (int ns = 0; ns < 4; ++ns)
#pragma unroll
            for (int e = 0; e < 4; ++e) acc[mt][ns][e] = 0.f;

#pragma unroll
    for (int ks = 0; ks < 8; ++ks) {
        const int k8 = ks * 16 + fk8;
        const uint32_t koff = ((k8 >> 6) << 7) + (((k8 & 63) << 1) ^ fswz);
        unsigned ah[2][4], al[2][4], bh[2][4], bl[2][4];
#pragma unroll
        for (int mt = 0; mt < 2; ++mt) {
            uint32_t ra = (uint32_t)(warpM * 32 + mt * 16 + fi) * 256 + koff;
            ldsm4(ah[mt], aHi + ra);
            ldsm4(al[mt], aLo + ra);
        }
#pragma unroll
        for (int nt = 0; nt < 2; ++nt) {
            uint32_t rb = (uint32_t)(warpN * 32 + nt * 16 + fi) * 256 + koff;
            ldsm4(bh[nt], bHi + rb);
            ldsm4(bl[nt], bLo + rb);
        }
#pragma unroll
        for (int mt = 0; mt < 2; ++mt)
#pragma unroll
            for (int nt = 0; nt < 2; ++nt) {
                mma16816(acc[mt][nt * 2],     ah[mt], bh[nt][0], bh[nt][2]);
                mma16816(acc[mt][nt * 2 + 1], ah[mt], bh[nt][1], bh[nt][3]);
                mma16816(acc[mt][nt * 2],     al[mt], bh[nt][0], bh[nt][2]);
                mma16816(acc[mt][nt * 2 + 1], al[mt], bh[nt][1], bh[nt][3]);
                mma16816(acc[mt][nt * 2],     ah[mt], bl[nt][0], bl[nt][2]);
                mma16816(acc[mt][nt * 2 + 1], ah[mt], bl[nt][1], bl[nt][3]);
            }
    }
}

// fp32 epilogue (optional rowcnt-scaled bias + relu); m0 = tile*64
__device__ __forceinline__ void epi_f32(
    float acc[2][4][4], float* __restrict__ C, const float* __restrict__ bias,
    const int* __restrict__ rowcnt, int m0, int M, int do_relu,
    int warpM, int warpN, int L)
{
#pragma unroll
    for (int mt = 0; mt < 2; ++mt) {
        int gr0 = m0 + warpM * 32 + mt * 16 + (L >> 2);
        int gr1 = gr0 + 8;
        float sc0 = 1.f, sc1 = 1.f;
        if (rowcnt) {
            if (gr0 < M) sc0 = (float)rowcnt[gr0];
            if (gr1 < M) sc1 = (float)rowcnt[gr1];
        }
#pragma unroll
        for (int ns = 0; ns < 4; ++ns) {
            int c = warpN * 32 + ns * 8 + (L & 3) * 2;
            float b0 = bias ? bias[c]     : 0.f;
            float b1 = bias ? bias[c + 1] : 0.f;
            float v00 = acc[mt][ns][0] + sc0 * b0;
            float v01 = acc[mt][ns][1] + sc0 * b1;
            float v10 = acc[mt][ns][2] + sc1 * b0;
            float v11 = acc[mt][ns][3] + sc1 * b1;
            if (do_relu) {
                v00 = fmaxf(v00, 0.f); v01 = fmaxf(v01, 0.f);
                v10 = fmaxf(v10, 0.f); v11 = fmaxf(v11, 0.f);
            }
            if (gr0 < M) *(float2*)(C + (size_t)gr0 * 128 + c) = make_float2(v00, v01);
            if (gr1 < M) *(float2*)(C + (size_t)gr1 * 128 + c) = make_float2(v10, v11);
        }
    }
}

// ---------------------------------------------------------------------------
// gemm_xa: fp32 A (64-row tiles) via cp.async; in-place convert to hi/lo
// images; mainloop; epilogue -> relu+bias, gmem hi/lo images.
// smem: [A 32K][W 64K] = 96 KB -> 2 CTAs/SM.
// ---------------------------------------------------------------------------
__global__ void __launch_bounds__(256, 2)
gemm_xa(const float* __restrict__ A, const uint4* __restrict__ Wimg,
        const float* __restrict__ bias, uint4* __restrict__ outHi,
        uint4* __restrict__ outLo, int M, int ntiles)
{
    extern __shared__ char smem[];
    const uint32_t sb = smem_u32(smem);
    const uint32_t sW = sb + 32768;

    const int tid = threadIdx.x;
    const int wid = tid >> 5;
    const int L   = tid & 31;
    const int warpM = wid >> 2, warpN = wid & 3;   // 2 x 4 warps
    const int fi = L & 15, fswz = (fi & 7) << 4, fk8 = (L >> 4) * 8;
    const int sr = tid >> 2, sq = tid & 3;         // 4 thr/row, 64 rows

    for (int i = tid; i < 4096; i += 256) cpa16(sW + i * 16, Wimg + i);
    {
        int m0 = blockIdx.x * 64;
        for (int i = tid; i < 2048; i += 256) {
            int r = i >> 5, cc = i & 31;
            int gr = m0 + r;
            int sz = (gr < M) ? 16 : 0;
            const float* src = A + (size_t)(gr < M ? gr : 0) * 128 + cc * 4;
            cpa16z(sb + f32_off(r, cc), src, sz);
        }
    }
    CP_COMMIT();

    for (int tile = blockIdx.x; tile < ntiles; tile += gridDim.x) {
        CP_WAIT0();
        __syncthreads();

        // fp32 -> regs
        float4 v[8];
#pragma unroll
        for (int j = 0; j < 8; ++j)
            v[j] = *(const float4*)(smem + f32_off(sr, sq * 8 + j));
        __syncthreads();

        // in-place convert: hi (0..16K) / lo (16..32K)
#pragma unroll
        for (int j = 0; j < 8; ++j) {
            float4 a = v[j];
            float hx = __bfloat162float(__float2bfloat16(a.x));
            float hy = __bfloat162float(__float2bfloat16(a.y));
            float hz = __bfloat162float(__float2bfloat16(a.z));
            float hw = __bfloat162float(__float2bfloat16(a.w));
            uint32_t off = img_off(sr, (sq * 8 + j) * 4);
            *(uint2*)(smem + off) =
                make_uint2(packbf(a.x, a.y), packbf(a.z, a.w));
            *(uint2*)(smem + 16384 + off) =
                make_uint2(packbf(a.x - hx, a.y - hy), packbf(a.z - hz, a.w - hw));
        }
        __syncthreads();

        float acc[2][4][4];
        tile_mainloop(acc, sb, sb + 16384, sW, sW + 32768,
                      warpM, warpN, fi, fswz, fk8);

        // epilogue: relu+bias, split, write gmem hi/lo images
        const int m0 = tile * 64;
        char* hB = (char*)outHi + (size_t)(tile >> 1) * 32768 + (tile & 1) * 16384;
        char* lB = (char*)outLo + (size_t)(tile >> 1) * 32768 + (tile & 1) * 16384;
#pragma unroll
        for (int mt = 0; mt < 2; ++mt) {
            int r0 = warpM * 32 + mt * 16 + (L >> 2);
            int r1 = r0 + 8;
#pragma unroll
            for (int ns = 0; ns < 4; ++ns) {
                int c = warpN * 32 + ns * 8 + (L & 3) * 2;
                float b0 = bias[c], b1 = bias[c + 1];
                float v00 = fmaxf(acc[mt][ns][0] + b0, 0.f);
                float v01 = fmaxf(acc[mt][ns][1] + b1, 0.f);
                float v10 = fmaxf(acc[mt][ns][2] + b0, 0.f);
                float v11 = fmaxf(acc[mt][ns][3] + b1, 0.f);
                if (m0 + r0 < M) {
                    uint32_t off = img_off(r0, c);
                    float h0 = __bfloat162float(__float2bfloat16(v00));
                    float h1 = __bfloat162float(__float2bfloat16(v01));
                    *(unsigned*)(hB + off) = packbf(v00, v01);
                    *(unsigned*)(lB + off) = packbf(v00 - h0, v01 - h1);
                }
                if (m0 + r1 < M) {
                    uint32_t off = img_off(r1, c);
                    float h0 = __bfloat162float(__float2bfloat16(v10));
                    float h1 = __bfloat162float(__float2bfloat16(v11));
                    *(unsigned*)(hB + off) = packbf(v10, v11);
                    *(unsigned*)(lB + off) = packbf(v10 - h0, v11 - h1);
                }
            }
        }
        __syncthreads();   // all reads of A buffer done before refill

        int nxt = tile + gridDim.x;
        if (nxt < ntiles) {
            int m0n = nxt * 64;
            for (int i = tid; i < 2048; i += 256) {
                int r = i >> 5, cc = i & 31;
                int gr = m0n + r;
                int sz = (gr < M) ? 16 : 0;
                const float* src = A + (size_t)(gr < M ? gr : 0) * 128 + cc * 4;
                cpa16z(sb + f32_off(r, cc), src, sz);
            }
        }
        CP_COMMIT();
    }
}

// ---------------------------------------------------------------------------
// gemm_b: image input (64-row tiles), cp.async single-buffered; fp32 output.
// smem: [A 32K][W 64K] = 96 KB -> 2 CTAs/SM.
// ---------------------------------------------------------------------------
__global__ void __launch_bounds__(256, 2)
gemm_b(const uint4* __restrict__ hiImg, const uint4* __restrict__ loImg,
       const uint4* __restrict__ Wimg, const float* __restrict__ bias,
       const int* __restrict__ rowcnt, float* __restrict__ C,
       int M, int ntiles, int do_relu)
{
    extern __shared__ char smem[];
    const uint32_t sb = smem_u32(smem);
    const uint32_t sW = sb + 32768;

    const int tid = threadIdx.x;
    const int wid = tid >> 5;
    const int L   = tid & 31;
    const int warpM = wid >> 2, warpN = wid & 3;
    const int fi = L & 15, fswz = (fi & 7) << 4, fk8 = (L >> 4) * 8;

    for (int i = tid; i < 4096; i += 256) cpa16(sW + i * 16, Wimg + i);
    {
        int t0 = blockIdx.x;
        if (t0 < ntiles) {
            const uint4* sH = hiImg + (size_t)(t0 >> 1) * 2048 + (t0 & 1) * 1024;
            const uint4* sL = loImg + (size_t)(t0 >> 1) * 2048 + (t0 & 1) * 1024;
            for (int i = tid; i < 1024; i += 256) {
                cpa16(sb + i * 16, sH + i);
                cpa16(sb + 16384 + i * 16, sL + i);
            }
        }
    }
    CP_COMMIT();

    for (int tile = blockIdx.x; tile < ntiles; tile += gridDim.x) {
        CP_WAIT0();
        __syncthreads();

        float acc[2][4][4];
        tile_mainloop(acc, sb, sb + 16384, sW, sW + 32768,
                      warpM, warpN, fi, fswz, fk8);

        epi_f32(acc, C, bias, rowcnt, tile * 64, M, do_relu, warpM, warpN, L);
        __syncthreads();   // reads of A buffer done

        int nxt = tile + gridDim.x;
        if (nxt < ntiles) {
            const uint4* sH = hiImg + (size_t)(nxt >> 1) * 2048 + (nxt & 1) * 1024;
            const uint4* sL = loImg + (size_t)(nxt >> 1) * 2048 + (nxt & 1) * 1024;
            for (int i = tid; i < 1024; i += 256) {
                cpa16(sb + i * 16, sH + i);
                cpa16(sb + 16384 + i * 16, sL + i);
            }
        }
        CP_COMMIT();
    }
}

// ---------------------------------------------------------------------------
// gemm_pq2: split grid. CTAs [0,148) -> P (W1a, +b1); [148,296) -> Q (W1b).
// ---------------------------------------------------------------------------
__global__ void __launch_bounds__(256, 2)
gemm_pq2(const uint4* __restrict__ hiImg, const uint4* __restrict__ loImg,
         const uint4* __restrict__ Wa, const uint4* __restrict__ Wb,
         const float* __restrict__ b1, float* __restrict__ P,
         float* __restrict__ Q, int M, int ntiles)
{
    extern __shared__ char smem[];
    const uint32_t sb = smem_u32(smem);
    const uint32_t sW = sb + 32768;

    const int half = (blockIdx.x >= 148) ? 1 : 0;
    const int base = blockIdx.x - half * 148;
    const uint4* Wimg = half ? Wb : Wa;
    float* C = half ? Q : P;
    const float* bias = half ? nullptr : b1;

    const int tid = threadIdx.x;
    const int wid = tid >> 5;
    const int L   = tid & 31;
    const int warpM = wid >> 2, warpN = wid & 3;
    const int fi = L & 15, fswz = (fi & 7) << 4, fk8 = (L >> 4) * 8;

    for (int i = tid; i < 4096; i += 256) cpa16(sW + i * 16, Wimg + i);
    {
        const uint4* sH = hiImg + (size_t)(base >> 1) * 2048 + (base & 1) * 1024;
        const uint4* sL = loImg + (size_t)(base >> 1) * 2048 + (base & 1) * 1024;
        for (int i = tid; i < 1024; i += 256) {
            cpa16(sb + i * 16, sH + i);
            cpa16(sb + 16384 + i * 16, sL + i);
        }
    }
    CP_COMMIT();

    for (int tile = base; tile < ntiles; tile += 148) {
        CP_WAIT0();
        __syncthreads();

        float acc[2][4][4];
        tile_mainloop(acc, sb, sb + 16384, sW, sW + 32768,
                      warpM, warpN, fi, fswz, fk8);

        epi_f32(acc, C, bias, nullptr, tile * 64, M, 0, warpM, warpN, L);
        __syncthreads();

        int nxt = tile + 148;
        if (nxt < ntiles) {
            const uint4* sH = hiImg + (size_t)(nxt >> 1) * 2048 + (nxt & 1) * 1024;
            const uint4* sL = loImg + (size_t)(nxt >> 1) * 2048 + (nxt & 1) * 1024;
            for (int i = tid; i < 1024; i += 256) {
                cpa16(sb + i * 16, sH + i);
                cpa16(sb + 16384 + i * 16, sL + i);
            }
        }
        CP_COMMIT();
    }
}

// ---------------------------------------------------------------------------
__global__ void __launch_bounds__(256)
zero_kernel()
{
    int idx = blockIdx.x * blockDim.x + threadIdx.x;
    int stride = gridDim.x * blockDim.x;
    for (int i = idx; i < NODES; i += stride) g_cnt[i] = 0;
    if (idx == 0) g_novf = 0;
}

__global__ void __launch_bounds__(256)
bucket_kernel(const int* __restrict__ ei)
{
    int e = blockIdx.x * blockDim.x + threadIdx.x;
    if (e >= EDGES) return;
    int s = ei[e];
    int d = ei[EDGES + e];
    int slot = atomicAdd(&g_cnt[d], 1);
    if (slot < CAP) {
        g_bucket[(size_t)d * CAP + slot] = s;
    } else {
        int o = atomicAdd(&g_novf, 1);
        if (o < OVFMAX) g_ovf[o] = make_int2(s, d);
    }
}

// Warp per node: S[d] = sum relu(P[d]+Q[src]); write S as bf16 hi/lo images.
__global__ void __launch_bounds__(256)
node_kernel()
{
    int d    = (blockIdx.x * blockDim.x + threadIdx.x) >> 5;
    int lane = threadIdx.x & 31;
    if (d >= NODES) return;

    int n = g_cnt[d];
    if (n > CAP) n = CAP;

    float4 p = ((const float4*)(g_P + (size_t)d * HID))[lane];
    float4 acc = make_float4(0.f, 0.f, 0.f, 0.f);
    const int* bkt = g_bucket + (size_t)d * CAP;
#pragma unroll 2
    for (int i = 0; i < n; ++i) {
        int s = __ldg(bkt + i);
        float4 q = ((const float4*)(g_Q + (size_t)s * HID))[lane];
        acc.x += fmaxf(p.x + q.x, 0.f);
        acc.y += fmaxf(p.y + q.y, 0.f);
        acc.z += fmaxf(p.z + q.z, 0.f);
        acc.w += fmaxf(p.w + q.w, 0.f);
    }
    int r = d & 127;
    uint32_t off = img_off(r, lane * 4);
    char* hB = (char*)g_sHi + (size_t)(d >> 7) * 32768;
    char* lB = (char*)g_sLo + (size_t)(d >> 7) * 32768;
    float hx = __bfloat162float(__float2bfloat16(acc.x));
    float hy = __bfloat162float(__float2bfloat16(acc.y));
    float hz = __bfloat162float(__float2bfloat16(acc.z));
    float hw = __bfloat162float(__float2bfloat16(acc.w));
    *(uint2*)(hB + off) = make_uint2(packbf(acc.x, acc.y), packbf(acc.z, acc.w));
    *(uint2*)(lB + off) = make_uint2(packbf(acc.x - hx, acc.y - hy),
                                     packbf(acc.z - hz, acc.w - hw));
}

// Serial overflow fixup (single warp; expected empty). RMW on S images.
__global__ void __launch_bounds__(32)
fixup_kernel()
{
    int total = g_novf;
    if (total > OVFMAX) total = OVFMAX;
    int lane = threadIdx.x;
    for (int j = 0; j < total; ++j) {
        int2 e = g_ovf[j];
        float4 p = ((const float4*)(g_P + (size_t)e.y * HID))[lane];
        float4 q = ((const float4*)(g_Q + (size_t)e.x * HID))[lane];
        int r = e.y & 127;
        uint32_t off = img_off(r, lane * 4);
        char* hB = (char*)g_sHi + (size_t)(e.y >> 7) * 32768;
        char* lB = (char*)g_sLo + (size_t)(e.y >> 7) * 32768;
        uint2 hh = *(uint2*)(hB + off);
        uint2 ll = *(uint2*)(lB + off);
        __nv_bfloat162 h0 = *(__nv_bfloat162*)&hh.x, h1 = *(__nv_bfloat162*)&hh.y;
        __nv_bfloat162 l0 = *(__nv_bfloat162*)&ll.x, l1 = *(__nv_bfloat162*)&ll.y;
        float vx = __bfloat162float(h0.x) + __bfloat162float(l0.x) + fmaxf(p.x + q.x, 0.f);
        float vy = __bfloat162float(h0.y) + __bfloat162float(l0.y) + fmaxf(p.y + q.y, 0.f);
        float vz = __bfloat162float(h1.x) + __bfloat162float(l1.x) + fmaxf(p.z + q.z, 0.f);
        float vw = __bfloat162float(h1.y) + __bfloat162float(l1.y) + fmaxf(p.w + q.w, 0.f);
        float hx = __bfloat162float(__float2bfloat16(vx));
        float hy = __bfloat162float(__float2bfloat16(vy));
        float hz = __bfloat162float(__float2bfloat16(vz));
        float hw = __bfloat162float(__float2bfloat16(vw));
        *(uint2*)(hB + off) = make_uint2(packbf(vx, vy), packbf(vz, vw));
        *(uint2*)(lB + off) = make_uint2(packbf(vx - hx, vy - hy),
                                         packbf(vz - hz, vw - hw));
        __syncwarp();
    }
}

__global__ void __launch_bounds__(256)
out_kernel(const float* __restrict__ H2, const float* __restrict__ Wc,
           const float* __restrict__ bc, float* __restrict__ out)
{
    int gw   = (blockIdx.x * blockDim.x + threadIdx.x) >> 5;
    int lane = threadIdx.x & 31;
    if (gw >= NODES) return;

    float4 hv  = ((const float4*)(H2 + (size_t)gw * HID))[lane];
    float4 w01 = ((const float4*)Wc)[lane * 2];
    float4 w23 = ((const float4*)Wc)[lane * 2 + 1];

    float a0 = hv.x * w01.x + hv.y * w01.z + hv.z * w23.x + hv.w * w23.z;
    float a1 = hv.x * w01.y + hv.y * w01.w + hv.z * w23.y + hv.w * w23.w;
#pragma unroll
    for (int off = 16; off > 0; off >>= 1) {
        a0 += __shfl_xor_sync(0xffffffffu, a0, off);
        a1 += __shfl_xor_sync(0xffffffffu, a1, off);
    }
    if (lane == 0) {
        out[(size_t)gw * 2]     = a0 + bc[0];
        out[(size_t)gw * 2 + 1] = a1 + bc[1];
    }
}

// ---------------------------------------------------------------------------
extern "C" void kernel_launch(void* const* d_in, const int* in_sizes, int n_in,
                              void* d_out, int out_size)
{
    const float* x    = (const float*)d_in[0];
    const int*   ei   = (const int*)d_in[1];
    const float* W_in = (const float*)d_in[2];
    const float* b_in = (const float*)d_in[3];
    const float* W1   = (const float*)d_in[4];
    const float* b1   = (const float*)d_in[5];
    const float* W2   = (const float*)d_in[6];
    const float* b2   = (const float*)d_in[7];
    const float* Wc   = (const float*)d_in[8];
    const float* bc   = (const float*)d_in[9];
    float*       out  = (float*)d_out;

    void *ph2, *pP, *pQ, *pcnt, *pWin, *pW1a, *pW1b, *pW2;
    void *phHi, *phLo, *psHi, *psLo;
    cudaGetSymbolAddress(&ph2,  g_h2);
    cudaGetSymbolAddress(&pP,   g_P);
    cudaGetSymbolAddress(&pQ,   g_Q);
    cudaGetSymbolAddress(&pcnt, g_cnt);
    cudaGetSymbolAddress(&pWin, g_iWin);
    cudaGetSymbolAddress(&pW1a, g_iW1a);
    cudaGetSymbolAddress(&pW1b, g_iW1b);
    cudaGetSymbolAddress(&pW2,  g_iW2);
    cudaGetSymbolAddress(&phHi, g_hHi);
    cudaGetSymbolAddress(&phLo, g_hLo);
    cudaGetSymbolAddress(&psHi, g_sHi);
    cudaGetSymbolAddress(&psLo, g_sLo);

    const int SMEM = 96 * 1024;
    cudaFuncSetAttribute(gemm_xa, cudaFuncAttributeMaxDynamicSharedMemorySize, SMEM);
    cudaFuncSetAttribute(gemm_b,  cudaFuncAttributeMaxDynamicSharedMemorySize, SMEM);
    cudaFuncSetAttribute(gemm_pq2, cudaFuncAttributeMaxDynamicSharedMemorySize, SMEM);

    const int M = NODES;
    const int GRID = 296;   // 2 CTAs/SM

    prep_kernel<<<256, 256>>>(W_in, W1, W2);
    zero_kernel<<<256, 256>>>();
    bucket_kernel<<<(EDGES + 255) / 256, 256>>>(ei);

    // 1) h images = split(relu(x @ Win + b_in))
    gemm_xa<<<GRID, 256, SMEM>>>(x, (const uint4*)pWin, b_in,
                                 (uint4*)phHi, (uint4*)phLo, M, NT64);
    // 2+3) P = h @ W1a + b1 ; Q = h @ W1b (split-grid fused)
    gemm_pq2<<<GRID, 256, SMEM>>>((const uint4*)phHi, (const uint4*)phLo,
                                  (const uint4*)pW1a, (const uint4*)pW1b,
                                  b1, (float*)pP, (float*)pQ, M, NT64);
    // 4) S images = split( sum_e relu(P[d]+Q[s]) )
    node_kernel<<<(NODES * 32 + 255) / 256, 256>>>();
    fixup_kernel<<<1, 32>>>();
    // 5) h2 = relu(S @ W2 + deg*b2)
    gemm_b<<<GRID, 256, SMEM>>>((const uint4*)psHi, (const uint4*)psLo,
                                (const uint4*)pW2, b2, (const int*)pcnt,
                                (float*)ph2, M, NT64, 1);
    // 6) out = h2 @ Wc + bc
    out_kernel<<<(NODES * 32 + 255) / 256, 256>>>((const float*)ph2, Wc, bc, out);
}

// round 14
// speedup vs baseline: 1.5373x; 1.0949x over previous
#include <cuda_runtime.h>
#include <cuda_bf16.h>
#include <cuda_fp16.h>
#include <cstdint>

#define NODES 50000
#define EDGES 800000
#define HID   128
#define CAP   128
#define OVFMAX 65536
#define NTILES  391           // ceil(50000/128)  (gmem image blocks)
#define NT64    782           // ceil(50000/64)   (GEMM tiles)

// ---------------------------------------------------------------------------
// Device-global scratch (no allocations allowed)
// ---------------------------------------------------------------------------
__device__ float  g_P[(size_t)NODES * HID];
__device__ __half g_Q[(size_t)NODES * HID];      // fp16 (gathered randomly)
__device__ int    g_cnt[NODES];
__device__ int    g_bucket[(size_t)NODES * CAP];
__device__ int2   g_ovf[OVFMAX];
__device__ int    g_novf;

// bf16 hi/lo "image" arrays: per 128-row block, 32 KB contiguous, element (r,k)
// at byte off = r*256 + ((k>>6)<<7) + (((k&63)<<1) ^ ((r&7)<<4)).
__device__ uint4 g_hHi[(size_t)NTILES * 2048];
__device__ uint4 g_hLo[(size_t)NTILES * 2048];
__device__ uint4 g_sHi[(size_t)NTILES * 2048];
__device__ uint4 g_sLo[(size_t)NTILES * 2048];

// Weight images (transposed, hi block 32KB then lo block 32KB)
__device__ uint4 g_iWin[4096];
__device__ uint4 g_iW1a[4096];
__device__ uint4 g_iW1b[4096];
__device__ uint4 g_iW2 [4096];

// ---------------------------------------------------------------------------
__device__ __forceinline__ uint32_t smem_u32(const void* p) {
    uint32_t a;
    asm("{ .reg .u64 t; cvta.to.shared.u64 t, %1; cvt.u32.u64 %0, t; }"
        : "=r"(a) : "l"(p));
    return a;
}
__device__ __forceinline__ unsigned packbf(float x, float y) {
    __nv_bfloat162 t = __floats2bfloat162_rn(x, y);
    return *reinterpret_cast<unsigned*>(&t);
}
__device__ __forceinline__ void ldsm4(unsigned* r, uint32_t addr) {
    asm volatile("ldmatrix.sync.aligned.m8n8.x4.shared.b16 {%0,%1,%2,%3}, [%4];"
                 : "=r"(r[0]), "=r"(r[1]), "=r"(r[2]), "=r"(r[3]) : "r"(addr));
}
__device__ __forceinline__ void mma16816(float* d, const unsigned* a,
                                         unsigned b0, unsigned b1) {
    asm volatile(
        "mma.sync.aligned.m16n8k16.row.col.f32.bf16.bf16.f32 "
        "{%0,%1,%2,%3},{%4,%5,%6,%7},{%8,%9},{%0,%1,%2,%3};"
        : "+f"(d[0]), "+f"(d[1]), "+f"(d[2]), "+f"(d[3])
        : "r"(a[0]), "r"(a[1]), "r"(a[2]), "r"(a[3]), "r"(b0), "r"(b1));
}
__device__ __forceinline__ void cpa16(uint32_t dst, const void* src) {
    asm volatile("cp.async.cg.shared.global [%0], [%1], 16;"
                 :: "r"(dst), "l"(src));
}
__device__ __forceinline__ void cpa16z(uint32_t dst, const void* src, int sz) {
    asm volatile("cp.async.cg.shared.global [%0], [%1], 16, %2;"
                 :: "r"(dst), "l"(src), "r"(sz));
}
#define CP_COMMIT() asm volatile("cp.async.commit_group;" ::: "memory")
#define CP_WAIT0()  asm volatile("cp.async.wait_group 0;" ::: "memory")

__device__ __forceinline__ uint32_t img_off(int r, int k) {
    return (uint32_t)r * 256 + ((k >> 6) << 7) + ((((k & 63) << 1)) ^ ((r & 7) << 4));
}
__device__ __forceinline__ uint32_t f32_off(int r, int cc) {
    return (uint32_t)r * 512 +
           (((uint32_t)cc * 16) ^ ((r & 7) << 4) ^ ((cc >> 3) << 4));
}

// ---------------------------------------------------------------------------
// Prep: weight images
// ---------------------------------------------------------------------------
__device__ __forceinline__ void img_write(uint4* img, int n, int k, float v) {
    __nv_bfloat16 hi = __float2bfloat16(v);
    float hf = __bfloat162float(hi);
    __nv_bfloat16 lo = __float2bfloat16(v - hf);
    uint32_t off = img_off(n, k);
    __nv_bfloat16* p = (__nv_bfloat16*)img;
    p[off >> 1]               = hi;
    p[128 * 128 + (off >> 1)] = lo;
}

__global__ void __launch_bounds__(256)
prep_kernel(const float* __restrict__ W_in, const float* __restrict__ W1,
            const float* __restrict__ W2)
{
    int idx = blockIdx.x * blockDim.x + threadIdx.x;
    int n = (idx >> 7) & 127, k = idx & 127;
    if (idx < 16384) {
        img_write(g_iWin, n, k, W_in[k * 128 + n]);
    } else if (idx < 32768) {
        img_write(g_iW1a, n, k, W1[k * 128 + n]);
    } else if (idx < 49152) {
        img_write(g_iW1b, n, k, W1[(128 + k) * 128 + n]);
    } else if (idx < 65536) {
        img_write(g_iW2, n, k, W2[k * 128 + n]);
    }
}

// ---------------------------------------------------------------------------
// Mainloop (64-row A tile): per k-step load Ah/Al/Bh/Bl frags once (8 ldsm4),
// issue 24 HMMAs (AhBh + AlBh + AhBl). Warp tile 32x32; 8 warps = 64x128.
// ---------------------------------------------------------------------------
__device__ __forceinline__ void tile_mainloop(
    float acc[2][4][4], uint32_t aHi, uint32_t aLo, uint32_t bHi, uint32_t bLo,
    int warpM, int warpN, int fi, int fswz, int fk8)
{
#pragma unroll
    for (int mt = 0; mt < 2; ++mt)
#pragma unroll
        for (int ns = 0; ns < 4; ++ns)
#pragma unroll
            for (int e = 0; e < 4; ++e) acc[mt][ns][e] = 0.f;

#pragma unroll
    for (int ks = 0; ks < 8; ++ks) {
        const int k8 = ks * 16 + fk8;
        const uint32_t koff = ((k8 >> 6) << 7) + (((k8 & 63) << 1) ^ fswz);
        unsigned ah[2][4], al[2][4], bh[2][4], bl[2][4];
#pragma unroll
        for (int mt = 0; mt < 2; ++mt) {
            uint32_t ra = (uint32_t)(warpM * 32 + mt * 16 + fi) * 256 + koff;
            ldsm4(ah[mt], aHi + ra);
            ldsm4(al[mt], aLo + ra);
        }
#pragma unroll
        for (int nt = 0; nt < 2; ++nt) {
            uint32_t rb = (uint32_t)(warpN * 32 + nt * 16 + fi) * 256 + koff;
            ldsm4(bh[nt], bHi + rb);
            ldsm4(bl[nt], bLo + rb);
        }
#pragma unroll
        for (int mt = 0; mt < 2; ++mt)
#pragma unroll
            for (int nt = 0; nt < 2; ++nt) {
                mma16816(acc[mt][nt * 2],     ah[mt], bh[nt][0], bh[nt][2]);
                mma16816(acc[mt][nt * 2 + 1], ah[mt], bh[nt][1], bh[nt][3]);
                mma16816(acc[mt][nt * 2],     al[mt], bh[nt][0], bh[nt][2]);
                mma16816(acc[mt][nt * 2 + 1], al[mt], bh[nt][1], bh[nt][3]);
                mma16816(acc[mt][nt * 2],     ah[mt], bl[nt][0], bl[nt][2]);
                mma16816(acc[mt][nt * 2 + 1], ah[mt], bl[nt][1], bl[nt][3]);
            }
    }
}

// ---------------------------------------------------------------------------
// gemm_xa: fp32 A (64-row tiles) via cp.async; in-place convert to hi/lo
// images; mainloop; epilogue -> relu+bias, gmem hi/lo images.
// smem: [A 32K][W 64K] = 96 KB -> 2 CTAs/SM.
// ---------------------------------------------------------------------------
__global__ void __launch_bounds__(256, 2)
gemm_xa(const float* __restrict__ A, const uint4* __restrict__ Wimg,
        const float* __restrict__ bias, uint4* __restrict__ outHi,
        uint4* __restrict__ outLo, int M, int ntiles)
{
    extern __shared__ char smem[];
    const uint32_t sb = smem_u32(smem);
    const uint32_t sW = sb + 32768;

    const int tid = threadIdx.x;
    const int wid = tid >> 5;
    const int L   = tid & 31;
    const int warpM = wid >> 2, warpN = wid & 3;
    const int fi = L & 15, fswz = (fi & 7) << 4, fk8 = (L >> 4) * 8;
    const int sr = tid >> 2, sq = tid & 3;

    for (int i = tid; i < 4096; i += 256) cpa16(sW + i * 16, Wimg + i);
    {
        int m0 = blockIdx.x * 64;
        for (int i = tid; i < 2048; i += 256) {
            int r = i >> 5, cc = i & 31;
            int gr = m0 + r;
            int sz = (gr < M) ? 16 : 0;
            const float* src = A + (size_t)(gr < M ? gr : 0) * 128 + cc * 4;
            cpa16z(sb + f32_off(r, cc), src, sz);
        }
    }
    CP_COMMIT();

    for (int tile = blockIdx.x; tile < ntiles; tile += gridDim.x) {
        CP_WAIT0();
        __syncthreads();

        float4 v[8];
#pragma unroll
        for (int j = 0; j < 8; ++j)
            v[j] = *(const float4*)(smem + f32_off(sr, sq * 8 + j));
        __syncthreads();

#pragma unroll
        for (int j = 0; j < 8; ++j) {
            float4 a = v[j];
            float hx = __bfloat162float(__float2bfloat16(a.x));
            float hy = __bfloat162float(__float2bfloat16(a.y));
            float hz = __bfloat162float(__float2bfloat16(a.z));
            float hw = __bfloat162float(__float2bfloat16(a.w));
            uint32_t off = img_off(sr, (sq * 8 + j) * 4);
            *(uint2*)(smem + off) =
                make_uint2(packbf(a.x, a.y), packbf(a.z, a.w));
            *(uint2*)(smem + 16384 + off) =
                make_uint2(packbf(a.x - hx, a.y - hy), packbf(a.z - hz, a.w - hw));
        }
        __syncthreads();

        float acc[2][4][4];
        tile_mainloop(acc, sb, sb + 16384, sW, sW + 32768,
                      warpM, warpN, fi, fswz, fk8);

        const int m0 = tile * 64;
        char* hB = (char*)outHi + (size_t)(tile >> 1) * 32768 + (tile & 1) * 16384;
        char* lB = (char*)outLo + (size_t)(tile >> 1) * 32768 + (tile & 1) * 16384;
#pragma unroll
        for (int mt = 0; mt < 2; ++mt) {
            int r0 = warpM * 32 + mt * 16 + (L >> 2);
            int r1 = r0 + 8;
#pragma unroll
            for (int ns = 0; ns < 4; ++ns) {
                int c = warpN * 32 + ns * 8 + (L & 3) * 2;
                float b0 = bias[c], b1 = bias[c + 1];
                float v00 = fmaxf(acc[mt][ns][0] + b0, 0.f);
                float v01 = fmaxf(acc[mt][ns][1] + b1, 0.f);
                float v10 = fmaxf(acc[mt][ns][2] + b0, 0.f);
                float v11 = fmaxf(acc[mt][ns][3] + b1, 0.f);
                if (m0 + r0 < M) {
                    uint32_t off = img_off(r0, c);
                    float h0 = __bfloat162float(__float2bfloat16(v00));
                    float h1 = __bfloat162float(__float2bfloat16(v01));
                    *(unsigned*)(hB + off) = packbf(v00, v01);
                    *(unsigned*)(lB + off) = packbf(v00 - h0, v01 - h1);
                }
                if (m0 + r1 < M) {
                    uint32_t off = img_off(r1, c);
                    float h0 = __bfloat162float(__float2bfloat16(v10));
                    float h1 = __bfloat162float(__float2bfloat16(v11));
                    *(unsigned*)(hB + off) = packbf(v10, v11);
                    *(unsigned*)(lB + off) = packbf(v10 - h0, v11 - h1);
                }
            }
        }
        __syncthreads();

        int nxt = tile + gridDim.x;
        if (nxt < ntiles) {
            int m0n = nxt * 64;
            for (int i = tid; i < 2048; i += 256) {
                int r = i >> 5, cc = i & 31;
                int gr = m0n + r;
                int sz = (gr < M) ? 16 : 0;
                const float* src = A + (size_t)(gr < M ? gr : 0) * 128 + cc * 4;
                cpa16z(sb + f32_off(r, cc), src, sz);
            }
        }
        CP_COMMIT();
    }
}

// ---------------------------------------------------------------------------
// gemm_pq2: split grid. CTAs [0,148) -> P (W1a, +b1, fp32); [148,296) -> Q
// (W1b, fp16). smem: [A 32K][W 64K] = 96 KB.
// ---------------------------------------------------------------------------
__global__ void __launch_bounds__(256, 2)
gemm_pq2(const uint4* __restrict__ hiImg, const uint4* __restrict__ loImg,
         const uint4* __restrict__ Wa, const uint4* __restrict__ Wb,
         const float* __restrict__ b1, float* __restrict__ P,
         __half* __restrict__ Q, int M, int ntiles)
{
    extern __shared__ char smem[];
    const uint32_t sb = smem_u32(smem);
    const uint32_t sW = sb + 32768;

    const int half = (blockIdx.x >= 148) ? 1 : 0;
    const int base = blockIdx.x - half * 148;
    const uint4* Wimg = half ? Wb : Wa;

    const int tid = threadIdx.x;
    const int wid = tid >> 5;
    const int L   = tid & 31;
    const int warpM = wid >> 2, warpN = wid & 3;
    const int fi = L & 15, fswz = (fi & 7) << 4, fk8 = (L >> 4) * 8;

    for (int i = tid; i < 4096; i += 256) cpa16(sW + i * 16, Wimg + i);
    {
        const uint4* sH = hiImg + (size_t)(base >> 1) * 2048 + (base & 1) * 1024;
        const uint4* sL = loImg + (size_t)(base >> 1) * 2048 + (base & 1) * 1024;
        for (int i = tid; i < 1024; i += 256) {
            cpa16(sb + i * 16, sH + i);
            cpa16(sb + 16384 + i * 16, sL + i);
        }
    }
    CP_COMMIT();

    for (int tile = base; tile < ntiles; tile += 148) {
        CP_WAIT0();
        __syncthreads();

        float acc[2][4][4];
        tile_mainloop(acc, sb, sb + 16384, sW, sW + 32768,
                      warpM, warpN, fi, fswz, fk8);

        const int m0 = tile * 64;
#pragma unroll
        for (int mt = 0; mt < 2; ++mt) {
            int gr0 = m0 + warpM * 32 + mt * 16 + (L >> 2);
            int gr1 = gr0 + 8;
#pragma unroll
            for (int ns = 0; ns < 4; ++ns) {
                int c = warpN * 32 + ns * 8 + (L & 3) * 2;
                if (half) {
                    // Q: fp16 store
                    if (gr0 < M) {
                        __half2 h = __floats2half2_rn(acc[mt][ns][0], acc[mt][ns][1]);
                        *(__half2*)(Q + (size_t)gr0 * 128 + c) = h;
                    }
                    if (gr1 < M) {
                        __half2 h = __floats2half2_rn(acc[mt][ns][2], acc[mt][ns][3]);
                        *(__half2*)(Q + (size_t)gr1 * 128 + c) = h;
                    }
                } else {
                    float b0 = b1[c], bb1 = b1[c + 1];
                    if (gr0 < M)
                        *(float2*)(P + (size_t)gr0 * 128 + c) =
                            make_float2(acc[mt][ns][0] + b0, acc[mt][ns][1] + bb1);
                    if (gr1 < M)
                        *(float2*)(P + (size_t)gr1 * 128 + c) =
                            make_float2(acc[mt][ns][2] + b0, acc[mt][ns][3] + bb1);
                }
            }
        }
        __syncthreads();

        int nxt = tile + 148;
        if (nxt < ntiles) {
            const uint4* sH = hiImg + (size_t)(nxt >> 1) * 2048 + (nxt & 1) * 1024;
            const uint4* sL = loImg + (size_t)(nxt >> 1) * 2048 + (nxt & 1) * 1024;
            for (int i = tid; i < 1024; i += 256) {
                cpa16(sb + i * 16, sH + i);
                cpa16(sb + 16384 + i * 16, sL + i);
            }
        }
        CP_COMMIT();
    }
}

// ---------------------------------------------------------------------------
// gemm_s2o: S images @ W2 -> h2 = relu(. + deg*b2) -> out = h2 @ Wc + bc.
// Fused GEMV epilogue: shfl-reduce over 4 lanes, smem-atomic over 4 warpN
// warps, single store per row. smem: [A 32K][W 64K][sOut 512B].
// ---------------------------------------------------------------------------
__global__ void __launch_bounds__(256, 2)
gemm_s2o(const uint4* __restrict__ hiImg, const uint4* __restrict__ loImg,
         const uint4* __restrict__ Wimg, const float* __restrict__ b2,
         const int* __restrict__ rowcnt, const float* __restrict__ Wc,
         const float* __restrict__ bc, float* __restrict__ out,
         int M, int ntiles)
{
    extern __shared__ char smem[];
    const uint32_t sb = smem_u32(smem);
    const uint32_t sW = sb + 32768;
    float* sOut = (float*)(smem + 98304);   // 64 rows x 2

    const int tid = threadIdx.x;
    const int wid = tid >> 5;
    const int L   = tid & 31;
    const int warpM = wid >> 2, warpN = wid & 3;
    const int fi = L & 15, fswz = (fi & 7) << 4, fk8 = (L >> 4) * 8;

    for (int i = tid; i < 4096; i += 256) cpa16(sW + i * 16, Wimg + i);
    {
        int t0 = blockIdx.x;
        if (t0 < ntiles) {
            const uint4* sH = hiImg + (size_t)(t0 >> 1) * 2048 + (t0 & 1) * 1024;
            const uint4* sL = loImg + (size_t)(t0 >> 1) * 2048 + (t0 & 1) * 1024;
            for (int i = tid; i < 1024; i += 256) {
                cpa16(sb + i * 16, sH + i);
                cpa16(sb + 16384 + i * 16, sL + i);
            }
        }
    }
    CP_COMMIT();

    for (int tile = blockIdx.x; tile < ntiles; tile += gridDim.x) {
        CP_WAIT0();
        __syncthreads();

        float acc[2][4][4];
        tile_mainloop(acc, sb, sb + 16384, sW, sW + 32768,
                      warpM, warpN, fi, fswz, fk8);

        if (tid < 128) sOut[tid] = 0.f;
        __syncthreads();

        const int m0 = tile * 64;
        float po[2][2][2];   // [mt][row01][outcol]
#pragma unroll
        for (int mt = 0; mt < 2; ++mt) {
            int gr0 = m0 + warpM * 32 + mt * 16 + (L >> 2);
            int gr1 = gr0 + 8;
            float sc0 = (gr0 < M) ? (float)rowcnt[gr0] : 0.f;
            float sc1 = (gr1 < M) ? (float)rowcnt[gr1] : 0.f;
            po[mt][0][0] = po[mt][0][1] = po[mt][1][0] = po[mt][1][1] = 0.f;
#pragma unroll
            for (int ns = 0; ns < 4; ++ns) {
                int c = warpN * 32 + ns * 8 + (L & 3) * 2;
                float b0 = b2[c], b1 = b2[c + 1];
                float v00 = fmaxf(acc[mt][ns][0] + sc0 * b0, 0.f);
                float v01 = fmaxf(acc[mt][ns][1] + sc0 * b1, 0.f);
                float v10 = fmaxf(acc[mt][ns][2] + sc1 * b0, 0.f);
                float v11 = fmaxf(acc[mt][ns][3] + sc1 * b1, 0.f);
                float2 w0 = *(const float2*)(Wc + c * 2);
                float2 w1 = *(const float2*)(Wc + (c + 1) * 2);
                po[mt][0][0] += v00 * w0.x + v01 * w1.x;
                po[mt][0][1] += v00 * w0.y + v01 * w1.y;
                po[mt][1][0] += v10 * w0.x + v11 * w1.x;
                po[mt][1][1] += v10 * w0.y + v11 * w1.y;
            }
            // reduce over 4 lanes sharing a row (L&3)
#pragma unroll
            for (int off = 1; off <= 2; off <<= 1) {
                po[mt][0][0] += __shfl_xor_sync(0xffffffffu, po[mt][0][0], off);
                po[mt][0][1] += __shfl_xor_sync(0xffffffffu, po[mt][0][1], off);
                po[mt][1][0] += __shfl_xor_sync(0xffffffffu, po[mt][1][0], off);
                po[mt][1][1] += __shfl_xor_sync(0xffffffffu, po[mt][1][1], off);
            }
            if ((L & 3) == 0) {
                int r0 = warpM * 32 + mt * 16 + (L >> 2);
                atomicAdd(&sOut[r0 * 2],           po[mt][0][0]);
                atomicAdd(&sOut[r0 * 2 + 1],       po[mt][0][1]);
                atomicAdd(&sOut[(r0 + 8) * 2],     po[mt][1][0]);
                atomicAdd(&sOut[(r0 + 8) * 2 + 1], po[mt][1][1]);
            }
        }
        __syncthreads();

        if (tid < 128) {
            int r = tid >> 1, k = tid & 1;
            int gr = m0 + r;
            if (gr < M) out[(size_t)gr * 2 + k] = sOut[tid] + bc[k];
        }
        __syncthreads();   // A + sOut reads done

        int nxt = tile + gridDim.x;
        if (nxt < ntiles) {
            const uint4* sH = hiImg + (size_t)(nxt >> 1) * 2048 + (nxt & 1) * 1024;
            const uint4* sL = loImg + (size_t)(nxt >> 1) * 2048 + (nxt & 1) * 1024;
            for (int i = tid; i < 1024; i += 256) {
                cpa16(sb + i * 16, sH + i);
                cpa16(sb + 16384 + i * 16, sL + i);
            }
        }
        CP_COMMIT();
    }
}

// ---------------------------------------------------------------------------
__global__ void __launch_bounds__(256)
zero_kernel()
{
    int idx = blockIdx.x * blockDim.x + threadIdx.x;
    int stride = gridDim.x * blockDim.x;
    for (int i = idx; i < NODES; i += stride) g_cnt[i] = 0;
    if (idx == 0) g_novf = 0;
}

__global__ void __launch_bounds__(256)
bucket_kernel(const int* __restrict__ ei)
{
    int e = blockIdx.x * blockDim.x + threadIdx.x;
    if (e >= EDGES) return;
    int s = ei[e];
    int d = ei[EDGES + e];
    int slot = atomicAdd(&g_cnt[d], 1);
    if (slot < CAP) {
        g_bucket[(size_t)d * CAP + slot] = s;
    } else {
        int o = atomicAdd(&g_novf, 1);
        if (o < OVFMAX) g_ovf[o] = make_int2(s, d);
    }
}

// Warp per node: S[d] = sum relu(P[d]+Q[src]); Q gathered as fp16.
// Write S as bf16 hi/lo images.
__global__ void __launch_bounds__(256)
node_kernel()
{
    int d    = (blockIdx.x * blockDim.x + threadIdx.x) >> 5;
    int lane = threadIdx.x & 31;
    if (d >= NODES) return;

    int n = g_cnt[d];
    if (n > CAP) n = CAP;

    float4 p = ((const float4*)(g_P + (size_t)d * HID))[lane];
    float4 acc = make_float4(0.f, 0.f, 0.f, 0.f);
    const int* bkt = g_bucket + (size_t)d * CAP;
#pragma unroll 2
    for (int i = 0; i < n; ++i) {
        int s = __ldg(bkt + i);
        uint2 qraw = ((const uint2*)(g_Q + (size_t)s * HID))[lane];
        __half2 q0 = *(__half2*)&qraw.x;
        __half2 q1 = *(__half2*)&qraw.y;
        float2 f0 = __half22float2(q0);
        float2 f1 = __half22float2(q1);
        acc.x += fmaxf(p.x + f0.x, 0.f);
        acc.y += fmaxf(p.y + f0.y, 0.f);
        acc.z += fmaxf(p.z + f1.x, 0.f);
        acc.w += fmaxf(p.w + f1.y, 0.f);
    }
    int r = d & 127;
    uint32_t off = img_off(r, lane * 4);
    char* hB = (char*)g_sHi + (size_t)(d >> 7) * 32768;
    char* lB = (char*)g_sLo + (size_t)(d >> 7) * 32768;
    float hx = __bfloat162float(__float2bfloat16(acc.x));
    float hy = __bfloat162float(__float2bfloat16(acc.y));
    float hz = __bfloat162float(__float2bfloat16(acc.z));
    float hw = __bfloat162float(__float2bfloat16(acc.w));
    *(uint2*)(hB + off) = make_uint2(packbf(acc.x, acc.y), packbf(acc.z, acc.w));
    *(uint2*)(lB + off) = make_uint2(packbf(acc.x - hx, acc.y - hy),
                                     packbf(acc.z - hz, acc.w - hw));
}

// Serial overflow fixup (single warp; expected empty). RMW on S images.
__global__ void __launch_bounds__(32)
fixup_kernel()
{
    int total = g_novf;
    if (total > OVFMAX) total = OVFMAX;
    int lane = threadIdx.x;
    for (int j = 0; j < total; ++j) {
        int2 e = g_ovf[j];
        float4 p = ((const float4*)(g_P + (size_t)e.y * HID))[lane];
        uint2 qraw = ((const uint2*)(g_Q + (size_t)e.x * HID))[lane];
        __half2 q0 = *(__half2*)&qraw.x;
        __half2 q1 = *(__half2*)&qraw.y;
        float2 f0 = __half22float2(q0);
        float2 f1 = __half22float2(q1);
        int r = e.y & 127;
        uint32_t off = img_off(r, lane * 4);
        char* hB = (char*)g_sHi + (size_t)(e.y >> 7) * 32768;
        char* lB = (char*)g_sLo + (size_t)(e.y >> 7) * 32768;
        uint2 hh = *(uint2*)(hB + off);
        uint2 ll = *(uint2*)(lB + off);
        __nv_bfloat162 h0 = *(__nv_bfloat162*)&hh.x, h1 = *(__nv_bfloat162*)&hh.y;
        __nv_bfloat162 l0 = *(__nv_bfloat162*)&ll.x, l1 = *(__nv_bfloat162*)&ll.y;
        float vx = __bfloat162float(h0.x) + __bfloat162float(l0.x) + fmaxf(p.x + f0.x, 0.f);
        float vy = __bfloat162float(h0.y) + __bfloat162float(l0.y) + fmaxf(p.y + f0.y, 0.f);
        float vz = __bfloat162float(h1.x) + __bfloat162float(l1.x) + fmaxf(p.z + f1.x, 0.f);
        float vw = __bfloat162float(h1.y) + __bfloat162float(l1.y) + fmaxf(p.w + f1.y, 0.f);
        float hx = __bfloat162float(__float2bfloat16(vx));
        float hy = __bfloat162float(__float2bfloat16(vy));
        float hz = __bfloat162float(__float2bfloat16(vz));
        float hw = __bfloat162float(__float2bfloat16(vw));
        *(uint2*)(hB + off) = make_uint2(packbf(vx, vy), packbf(vz, vw));
        *(uint2*)(lB + off) = make_uint2(packbf(vx - hx, vy - hy),
                                         packbf(vz - hz, vw - hw));
        __syncwarp();
    }
}

// ---------------------------------------------------------------------------
extern "C" void kernel_launch(void* const* d_in, const int* in_sizes, int n_in,
                              void* d_out, int out_size)
{
    const float* x    = (const float*)d_in[0];
    const int*   ei   = (const int*)d_in[1];
    const float* W_in = (const float*)d_in[2];
    const float* b_in = (const float*)d_in[3];
    const float* W1   = (const float*)d_in[4];
    const float* b1   = (const float*)d_in[5];
    const float* W2   = (const float*)d_in[6];
    const float* b2   = (const float*)d_in[7];
    const float* Wc   = (const float*)d_in[8];
    const float* bc   = (const float*)d_in[9];
    float*       out  = (float*)d_out;

    void *pP, *pQ, *pcnt, *pWin, *pW1a, *pW1b, *pW2;
    void *phHi, *phLo, *psHi, *psLo;
    cudaGetSymbolAddress(&pP,   g_P);
    cudaGetSymbolAddress(&pQ,   g_Q);
    cudaGetSymbolAddress(&pcnt, g_cnt);
    cudaGetSymbolAddress(&pWin, g_iWin);
    cudaGetSymbolAddress(&pW1a, g_iW1a);
    cudaGetSymbolAddress(&pW1b, g_iW1b);
    cudaGetSymbolAddress(&pW2,  g_iW2);
    cudaGetSymbolAddress(&phHi, g_hHi);
    cudaGetSymbolAddress(&phLo, g_hLo);
    cudaGetSymbolAddress(&psHi, g_sHi);
    cudaGetSymbolAddress(&psLo, g_sLo);

    const int SMEM   = 96 * 1024;
    const int SMEM_O = 96 * 1024 + 1024;   // + sOut
    cudaFuncSetAttribute(gemm_xa, cudaFuncAttributeMaxDynamicSharedMemorySize, SMEM);
    cudaFuncSetAttribute(gemm_pq2, cudaFuncAttributeMaxDynamicSharedMemorySize, SMEM);
    cudaFuncSetAttribute(gemm_s2o, cudaFuncAttributeMaxDynamicSharedMemorySize, SMEM_O);

    const int M = NODES;
    const int GRID = 296;   // 2 CTAs/SM

    prep_kernel<<<256, 256>>>(W_in, W1, W2);
    zero_kernel<<<256, 256>>>();
    bucket_kernel<<<(EDGES + 255) / 256, 256>>>(ei);

    // 1) h images = split(relu(x @ Win + b_in))
    gemm_xa<<<GRID, 256, SMEM>>>(x, (const uint4*)pWin, b_in,
                                 (uint4*)phHi, (uint4*)phLo, M, NT64);
    // 2+3) P = h @ W1a + b1 (fp32) ; Q = h @ W1b (fp16)
    gemm_pq2<<<GRID, 256, SMEM>>>((const uint4*)phHi, (const uint4*)phLo,
                                  (const uint4*)pW1a, (const uint4*)pW1b,
                                  b1, (float*)pP, (__half*)pQ, M, NT64);
    // 4) S images = split( sum_e relu(P[d]+Q[s]) )
    node_kernel<<<(NODES * 32 + 255) / 256, 256>>>();
    fixup_kernel<<<1, 32>>>();
    // 5+6) out = relu(S @ W2 + deg*b2) @ Wc + bc   (fused)
    gemm_s2o<<<GRID, 256, SMEM_O>>>((const uint4*)psHi, (const uint4*)psLo,
                                    (const uint4*)pW2, b2, (const int*)pcnt,
                                    Wc, bc, out, M, NT64);
}

// round 15
// speedup vs baseline: 1.8515x; 1.2044x over previous
#include <cuda_runtime.h>
#include <cuda_fp16.h>
#include <cstdint>

#define NODES 50000
#define EDGES 800000
#define HID   128
#define CAP   128
#define OVFMAX 65536
#define NT64    782           // ceil(50000/64)  (GEMM tiles / image blocks)

// ---------------------------------------------------------------------------
// Device-global scratch (no allocations allowed)
// ---------------------------------------------------------------------------
__device__ float  g_P[(size_t)NODES * HID];
__device__ __half g_Q[(size_t)NODES * HID];
__device__ int    g_cnt[NODES];
__device__ int    g_bucket[(size_t)NODES * CAP];
__device__ int2   g_ovf[OVFMAX];
__device__ int    g_novf;

// fp16 single-image arrays: per 64-row tile, 16 KB contiguous; element (r,k)
// at byte off = r*256 + ((k>>6)<<7) + (((k&63)<<1) ^ ((r&7)<<4)).
__device__ uint4 g_hF[(size_t)NT64 * 1024];
__device__ uint4 g_sF[(size_t)NT64 * 1024];

// Weight images (transposed, fp16 hi block 32KB then fp16 lo block 32KB)
__device__ uint4 g_iWin[4096];
__device__ uint4 g_iW1a[4096];
__device__ uint4 g_iW1b[4096];
__device__ uint4 g_iW2 [4096];

// ---------------------------------------------------------------------------
__device__ __forceinline__ uint32_t smem_u32(const void* p) {
    uint32_t a;
    asm("{ .reg .u64 t; cvta.to.shared.u64 t, %1; cvt.u32.u64 %0, t; }"
        : "=r"(a) : "l"(p));
    return a;
}
__device__ __forceinline__ unsigned packh2(float x, float y) {
    __half2 t = __floats2half2_rn(x, y);
    return *reinterpret_cast<unsigned*>(&t);
}
__device__ __forceinline__ void ldsm4(unsigned* r, uint32_t addr) {
    asm volatile("ldmatrix.sync.aligned.m8n8.x4.shared.b16 {%0,%1,%2,%3}, [%4];"
                 : "=r"(r[0]), "=r"(r[1]), "=r"(r[2]), "=r"(r[3]) : "r"(addr));
}
__device__ __forceinline__ void mmah(float* d, const unsigned* a,
                                     unsigned b0, unsigned b1) {
    asm volatile(
        "mma.sync.aligned.m16n8k16.row.col.f32.f16.f16.f32 "
        "{%0,%1,%2,%3},{%4,%5,%6,%7},{%8,%9},{%0,%1,%2,%3};"
        : "+f"(d[0]), "+f"(d[1]), "+f"(d[2]), "+f"(d[3])
        : "r"(a[0]), "r"(a[1]), "r"(a[2]), "r"(a[3]), "r"(b0), "r"(b1));
}
__device__ __forceinline__ void cpa16(uint32_t dst, const void* src) {
    asm volatile("cp.async.cg.shared.global [%0], [%1], 16;"
                 :: "r"(dst), "l"(src));
}
__device__ __forceinline__ void cpa16z(uint32_t dst, const void* src, int sz) {
    asm volatile("cp.async.cg.shared.global [%0], [%1], 16, %2;"
                 :: "r"(dst), "l"(src), "r"(sz));
}
#define CP_COMMIT() asm volatile("cp.async.commit_group;" ::: "memory")
#define CP_WAIT0()  asm volatile("cp.async.wait_group 0;" ::: "memory")

__device__ __forceinline__ uint32_t img_off(int r, int k) {
    return (uint32_t)r * 256 + ((k >> 6) << 7) + ((((k & 63) << 1)) ^ ((r & 7) << 4));
}
__device__ __forceinline__ uint32_t f32_off(int r, int cc) {
    return (uint32_t)r * 512 +
           (((uint32_t)cc * 16) ^ ((r & 7) << 4) ^ ((cc >> 3) << 4));
}

// ---------------------------------------------------------------------------
// Prep: weight images (fp16 hi/lo)
// ---------------------------------------------------------------------------
__device__ __forceinline__ void img_write(uint4* img, int n, int k, float v) {
    __half hi = __float2half_rn(v);
    __half lo = __float2half_rn(v - __half2float(hi));
    uint32_t off = img_off(n, k);
    __half* p = (__half*)img;
    p[off >> 1]               = hi;
    p[128 * 128 + (off >> 1)] = lo;
}

__global__ void __launch_bounds__(256)
prep_kernel(const float* __restrict__ W_in, const float* __restrict__ W1,
            const float* __restrict__ W2)
{
    int idx = blockIdx.x * blockDim.x + threadIdx.x;
    int n = (idx >> 7) & 127, k = idx & 127;
    if (idx < 16384) {
        img_write(g_iWin, n, k, W_in[k * 128 + n]);
    } else if (idx < 32768) {
        img_write(g_iW1a, n, k, W1[k * 128 + n]);
    } else if (idx < 49152) {
        img_write(g_iW1b, n, k, W1[(128 + k) * 128 + n]);
    } else if (idx < 65536) {
        img_write(g_iW2, n, k, W2[k * 128 + n]);
    }
}

// ---------------------------------------------------------------------------
// fp16 mainloop: per k-step 6 ldsm4 (a, Wh, Wl), 16 HMMAs (A*Wh + A*Wl).
// CTA tile 64x128, 8 warps of 32x32.
// ---------------------------------------------------------------------------
__device__ __forceinline__ void tile_ml16(
    float acc[2][4][4], uint32_t aImg, uint32_t bHi, uint32_t bLo,
    int warpM, int warpN, int fi, int fswz, int fk8)
{
#pragma unroll
    for (int mt = 0; mt < 2; ++mt)
#pragma unroll
        for (int ns = 0; ns < 4; ++ns)
#pragma unroll
            for (int e = 0; e < 4; ++e) acc[mt][ns][e] = 0.f;

#pragma unroll
    for (int ks = 0; ks < 8; ++ks) {
        const int k8 = ks * 16 + fk8;
        const uint32_t koff = ((k8 >> 6) << 7) + (((k8 & 63) << 1) ^ fswz);
        unsigned a[2][4], bh[2][4], bl[2][4];
#pragma unroll
        for (int mt = 0; mt < 2; ++mt)
            ldsm4(a[mt], aImg + (uint32_t)(warpM * 32 + mt * 16 + fi) * 256 + koff);
#pragma unroll
        for (int nt = 0; nt < 2; ++nt) {
            uint32_t rb = (uint32_t)(warpN * 32 + nt * 16 + fi) * 256 + koff;
            ldsm4(bh[nt], bHi + rb);
            ldsm4(bl[nt], bLo + rb);
        }
#pragma unroll
        for (int mt = 0; mt < 2; ++mt)
#pragma unroll
            for (int nt = 0; nt < 2; ++nt) {
                mmah(acc[mt][nt * 2],     a[mt], bh[nt][0], bh[nt][2]);
                mmah(acc[mt][nt * 2 + 1], a[mt], bh[nt][1], bh[nt][3]);
                mmah(acc[mt][nt * 2],     a[mt], bl[nt][0], bl[nt][2]);
                mmah(acc[mt][nt * 2 + 1], a[mt], bl[nt][1], bl[nt][3]);
            }
    }
}

// ---------------------------------------------------------------------------
// gemm_xa: fp32 x (64-row tiles) via cp.async; convert to fp16 image in smem;
// mainloop; epilogue -> relu+bias -> gmem fp16 image.
// smem: [buf 32K][W 64K] = 96 KB -> 2 CTAs/SM.
// ---------------------------------------------------------------------------
__global__ void __launch_bounds__(256, 2)
gemm_xa(const float* __restrict__ A, const uint4* __restrict__ Wimg,
        const float* __restrict__ bias, uint4* __restrict__ outF,
        int M, int ntiles)
{
    extern __shared__ char smem[];
    const uint32_t sb = smem_u32(smem);
    const uint32_t sW = sb + 32768;

    const int tid = threadIdx.x;
    const int wid = tid >> 5;
    const int L   = tid & 31;
    const int warpM = wid >> 2, warpN = wid & 3;
    const int fi = L & 15, fswz = (fi & 7) << 4, fk8 = (L >> 4) * 8;
    const int sr = tid >> 2, sq = tid & 3;

    for (int i = tid; i < 4096; i += 256) cpa16(sW + i * 16, Wimg + i);
    {
        int m0 = blockIdx.x * 64;
        for (int i = tid; i < 2048; i += 256) {
            int r = i >> 5, cc = i & 31;
            int gr = m0 + r;
            int sz = (gr < M) ? 16 : 0;
            const float* src = A + (size_t)(gr < M ? gr : 0) * 128 + cc * 4;
            cpa16z(sb + f32_off(r, cc), src, sz);
        }
    }
    CP_COMMIT();

    for (int tile = blockIdx.x; tile < ntiles; tile += gridDim.x) {
        CP_WAIT0();
        __syncthreads();

        float4 v[8];
#pragma unroll
        for (int j = 0; j < 8; ++j)
            v[j] = *(const float4*)(smem + f32_off(sr, sq * 8 + j));
        __syncthreads();

        // write fp16 image into first 16K of buf
#pragma unroll
        for (int j = 0; j < 8; ++j) {
            float4 a = v[j];
            uint32_t off = img_off(sr, (sq * 8 + j) * 4);
            *(uint2*)(smem + off) =
                make_uint2(packh2(a.x, a.y), packh2(a.z, a.w));
        }
        __syncthreads();

        float acc[2][4][4];
        tile_ml16(acc, sb, sW, sW + 32768, warpM, warpN, fi, fswz, fk8);

        const int m0 = tile * 64;
        char* fB = (char*)outF + (size_t)tile * 16384;
#pragma unroll
        for (int mt = 0; mt < 2; ++mt) {
            int r0 = warpM * 32 + mt * 16 + (L >> 2);
            int r1 = r0 + 8;
#pragma unroll
            for (int ns = 0; ns < 4; ++ns) {
                int c = warpN * 32 + ns * 8 + (L & 3) * 2;
                float b0 = bias[c], b1 = bias[c + 1];
                float v00 = fmaxf(acc[mt][ns][0] + b0, 0.f);
                float v01 = fmaxf(acc[mt][ns][1] + b1, 0.f);
                float v10 = fmaxf(acc[mt][ns][2] + b0, 0.f);
                float v11 = fmaxf(acc[mt][ns][3] + b1, 0.f);
                if (m0 + r0 < M)
                    *(unsigned*)(fB + img_off(r0, c)) = packh2(v00, v01);
                if (m0 + r1 < M)
                    *(unsigned*)(fB + img_off(r1, c)) = packh2(v10, v11);
            }
        }
        __syncthreads();   // all buf reads done before refill

        int nxt = tile + gridDim.x;
        if (nxt < ntiles) {
            int m0n = nxt * 64;
            for (int i = tid; i < 2048; i += 256) {
                int r = i >> 5, cc = i & 31;
                int gr = m0n + r;
                int sz = (gr < M) ? 16 : 0;
                const float* src = A + (size_t)(gr < M ? gr : 0) * 128 + cc * 4;
                cpa16z(sb + f32_off(r, cc), src, sz);
            }
        }
        CP_COMMIT();
    }
}

// ---------------------------------------------------------------------------
// gemm_pq2: split grid. CTAs [0,148) -> P (W1a, +b1, fp32); [148,296) -> Q
// (W1b, fp16). Double-buffered A. smem: [A0 16K][A1 16K][W 64K] = 96 KB.
// ---------------------------------------------------------------------------
__global__ void __launch_bounds__(256, 2)
gemm_pq2(const uint4* __restrict__ aImgG, const uint4* __restrict__ Wa,
         const uint4* __restrict__ Wb, const float* __restrict__ b1,
         float* __restrict__ P, __half* __restrict__ Q, int M, int ntiles)
{
    extern __shared__ char smem[];
    const uint32_t sb = smem_u32(smem);
    const uint32_t sW = sb + 32768;

    const int half = (blockIdx.x >= 148) ? 1 : 0;
    const int base = blockIdx.x - half * 148;
    const uint4* Wimg = half ? Wb : Wa;

    const int tid = threadIdx.x;
    const int wid = tid >> 5;
    const int L   = tid & 31;
    const int warpM = wid >> 2, warpN = wid & 3;
    const int fi = L & 15, fswz = (fi & 7) << 4, fk8 = (L >> 4) * 8;

    for (int i = tid; i < 4096; i += 256) cpa16(sW + i * 16, Wimg + i);
    {
        const uint4* srcA = aImgG + (size_t)base * 1024;
        for (int i = tid; i < 1024; i += 256) cpa16(sb + i * 16, srcA + i);
    }
    CP_COMMIT();

    int cur = 0;
    for (int tile = base; tile < ntiles; tile += 148) {
        CP_WAIT0();
        __syncthreads();

        int nxt = tile + 148;
        if (nxt < ntiles) {
            uint32_t dst = sb + (cur ^ 1) * 16384;
            const uint4* srcA = aImgG + (size_t)nxt * 1024;
            for (int i = tid; i < 1024; i += 256) cpa16(dst + i * 16, srcA + i);
        }
        CP_COMMIT();

        float acc[2][4][4];
        tile_ml16(acc, sb + cur * 16384, sW, sW + 32768,
                  warpM, warpN, fi, fswz, fk8);

        const int m0 = tile * 64;
#pragma unroll
        for (int mt = 0; mt < 2; ++mt) {
            int gr0 = m0 + warpM * 32 + mt * 16 + (L >> 2);
            int gr1 = gr0 + 8;
#pragma unroll
            for (int ns = 0; ns < 4; ++ns) {
                int c = warpN * 32 + ns * 8 + (L & 3) * 2;
                if (half) {
                    if (gr0 < M)
                        *(unsigned*)(Q + (size_t)gr0 * 128 + c) =
                            packh2(acc[mt][ns][0], acc[mt][ns][1]);
                    if (gr1 < M)
                        *(unsigned*)(Q + (size_t)gr1 * 128 + c) =
                            packh2(acc[mt][ns][2], acc[mt][ns][3]);
                } else {
                    float b0 = b1[c], bb1 = b1[c + 1];
                    if (gr0 < M)
                        *(float2*)(P + (size_t)gr0 * 128 + c) =
                            make_float2(acc[mt][ns][0] + b0, acc[mt][ns][1] + bb1);
                    if (gr1 < M)
                        *(float2*)(P + (size_t)gr1 * 128 + c) =
                            make_float2(acc[mt][ns][2] + b0, acc[mt][ns][3] + bb1);
                }
            }
        }
        cur ^= 1;
    }
}

// ---------------------------------------------------------------------------
// gemm_s2o: S image @ W2 -> relu(.+deg*b2) -> @Wc + bc -> out. Fused GEMV
// epilogue. Double-buffered A. smem: [A0 16K][A1 16K][W 64K][sOut 512B].
// ---------------------------------------------------------------------------
__global__ void __launch_bounds__(256, 2)
gemm_s2o(const uint4* __restrict__ aImgG, const uint4* __restrict__ Wimg,
         const float* __restrict__ b2, const int* __restrict__ rowcnt,
         const float* __restrict__ Wc, const float* __restrict__ bc,
         float* __restrict__ out, int M, int ntiles)
{
    extern __shared__ char smem[];
    const uint32_t sb = smem_u32(smem);
    const uint32_t sW = sb + 32768;
    float* sOut = (float*)(smem + 98304);

    const int tid = threadIdx.x;
    const int wid = tid >> 5;
    const int L   = tid & 31;
    const int warpM = wid >> 2, warpN = wid & 3;
    const int fi = L & 15, fswz = (fi & 7) << 4, fk8 = (L >> 4) * 8;

    for (int i = tid; i < 4096; i += 256) cpa16(sW + i * 16, Wimg + i);
    {
        int t0 = blockIdx.x;
        if (t0 < ntiles) {
            const uint4* srcA = aImgG + (size_t)t0 * 1024;
            for (int i = tid; i < 1024; i += 256) cpa16(sb + i * 16, srcA + i);
        }
    }
    CP_COMMIT();

    int cur = 0;
    for (int tile = blockIdx.x; tile < ntiles; tile += gridDim.x) {
        CP_WAIT0();
        __syncthreads();

        int nxt = tile + gridDim.x;
        if (nxt < ntiles) {
            uint32_t dst = sb + (cur ^ 1) * 16384;
            const uint4* srcA = aImgG + (size_t)nxt * 1024;
            for (int i = tid; i < 1024; i += 256) cpa16(dst + i * 16, srcA + i);
        }
        CP_COMMIT();

        float acc[2][4][4];
        tile_ml16(acc, sb + cur * 16384, sW, sW + 32768,
                  warpM, warpN, fi, fswz, fk8);

        if (tid < 128) sOut[tid] = 0.f;
        __syncthreads();

        const int m0 = tile * 64;
#pragma unroll
        for (int mt = 0; mt < 2; ++mt) {
            int gr0 = m0 + warpM * 32 + mt * 16 + (L >> 2);
            int gr1 = gr0 + 8;
            float sc0 = (gr0 < M) ? (float)rowcnt[gr0] : 0.f;
            float sc1 = (gr1 < M) ? (float)rowcnt[gr1] : 0.f;
            float p00 = 0.f, p01 = 0.f, p10 = 0.f, p11 = 0.f;
#pragma unroll
            for (int ns = 0; ns < 4; ++ns) {
                int c = warpN * 32 + ns * 8 + (L & 3) * 2;
                float b0 = b2[c], b1 = b2[c + 1];
                float v00 = fmaxf(acc[mt][ns][0] + sc0 * b0, 0.f);
                float v01 = fmaxf(acc[mt][ns][1] + sc0 * b1, 0.f);
                float v10 = fmaxf(acc[mt][ns][2] + sc1 * b0, 0.f);
                float v11 = fmaxf(acc[mt][ns][3] + sc1 * b1, 0.f);
                float2 w0 = *(const float2*)(Wc + c * 2);
                float2 w1 = *(const float2*)(Wc + (c + 1) * 2);
                p00 += v00 * w0.x + v01 * w1.x;
                p01 += v00 * w0.y + v01 * w1.y;
                p10 += v10 * w0.x + v11 * w1.x;
                p11 += v10 * w0.y + v11 * w1.y;
            }
#pragma unroll
            for (int off = 1; off <= 2; off <<= 1) {
                p00 += __shfl_xor_sync(0xffffffffu, p00, off);
                p01 += __shfl_xor_sync(0xffffffffu, p01, off);
                p10 += __shfl_xor_sync(0xffffffffu, p10, off);
                p11 += __shfl_xor_sync(0xffffffffu, p11, off);
            }
            if ((L & 3) == 0) {
                int r0 = warpM * 32 + mt * 16 + (L >> 2);
                atomicAdd(&sOut[r0 * 2],           p00);
                atomicAdd(&sOut[r0 * 2 + 1],       p01);
                atomicAdd(&sOut[(r0 + 8) * 2],     p10);
                atomicAdd(&sOut[(r0 + 8) * 2 + 1], p11);
            }
        }
        __syncthreads();

        if (tid < 128) {
            int r = tid >> 1, k = tid & 1;
            int gr = m0 + r;
            if (gr < M) out[(size_t)gr * 2 + k] = sOut[tid] + bc[k];
        }
        cur ^= 1;
    }
}

// ---------------------------------------------------------------------------
__global__ void __launch_bounds__(256)
zero_kernel()
{
    int idx = blockIdx.x * blockDim.x + threadIdx.x;
    int stride = gridDim.x * blockDim.x;
    for (int i = idx; i < NODES; i += stride) g_cnt[i] = 0;
    if (idx == 0) g_novf = 0;
}

__global__ void __launch_bounds__(256)
bucket_kernel(const int* __restrict__ ei)
{
    int e = blockIdx.x * blockDim.x + threadIdx.x;
    if (e >= EDGES) return;
    int s = ei[e];
    int d = ei[EDGES + e];
    int slot = atomicAdd(&g_cnt[d], 1);
    if (slot < CAP) {
        g_bucket[(size_t)d * CAP + slot] = s;
    } else {
        int o = atomicAdd(&g_novf, 1);
        if (o < OVFMAX) g_ovf[o] = make_int2(s, d);
    }
}

// Warp per node: S[d] = sum relu(P[d]+Q[src]); write S as fp16 image.
__global__ void __launch_bounds__(256)
node_kernel()
{
    int d    = (blockIdx.x * blockDim.x + threadIdx.x) >> 5;
    int lane = threadIdx.x & 31;
    if (d >= NODES) return;

    int n = g_cnt[d];
    if (n > CAP) n = CAP;

    float4 p = ((const float4*)(g_P + (size_t)d * HID))[lane];
    float4 acc = make_float4(0.f, 0.f, 0.f, 0.f);
    const int* bkt = g_bucket + (size_t)d * CAP;
#pragma unroll 2
    for (int i = 0; i < n; ++i) {
        int s = __ldg(bkt + i);
        uint2 qraw = ((const uint2*)(g_Q + (size_t)s * HID))[lane];
        __half2 q0 = *(__half2*)&qraw.x;
        __half2 q1 = *(__half2*)&qraw.y;
        float2 f0 = __half22float2(q0);
        float2 f1 = __half22float2(q1);
        acc.x += fmaxf(p.x + f0.x, 0.f);
        acc.y += fmaxf(p.y + f0.y, 0.f);
        acc.z += fmaxf(p.z + f1.x, 0.f);
        acc.w += fmaxf(p.w + f1.y, 0.f);
    }
    int r = d & 63;
    char* base = (char*)g_sF + (size_t)(d >> 6) * 16384;
    *(uint2*)(base + img_off(r, lane * 4)) =
        make_uint2(packh2(acc.x, acc.y), packh2(acc.z, acc.w));
}

// Serial overflow fixup (single warp; expected empty). RMW on S image.
__global__ void __launch_bounds__(32)
fixup_kernel()
{
    int total = g_novf;
    if (total > OVFMAX) total = OVFMAX;
    int lane = threadIdx.x;
    for (int j = 0; j < total; ++j) {
        int2 e = g_ovf[j];
        float4 p = ((const float4*)(g_P + (size_t)e.y * HID))[lane];
        uint2 qraw = ((const uint2*)(g_Q + (size_t)e.x * HID))[lane];
        __half2 q0 = *(__half2*)&qraw.x;
        __half2 q1 = *(__half2*)&qraw.y;
        float2 f0 = __half22float2(q0);
        float2 f1 = __half22float2(q1);
        int r = e.y & 63;
        char* base = (char*)g_sF + (size_t)(e.y >> 6) * 16384;
        uint2 sv = *(uint2*)(base + img_off(r, lane * 4));
        __half2 s0 = *(__half2*)&sv.x;
        __half2 s1 = *(__half2*)&sv.y;
        float vx = __half2float(s0.x) + fmaxf(p.x + f0.x, 0.f);
        float vy = __half2float(s0.y) + fmaxf(p.y + f0.y, 0.f);
        float vz = __half2float(s1.x) + fmaxf(p.z + f1.x, 0.f);
        float vw = __half2float(s1.y) + fmaxf(p.w + f1.y, 0.f);
        *(uint2*)(base + img_off(r, lane * 4)) =
            make_uint2(packh2(vx, vy), packh2(vz, vw));
        __syncwarp();
    }
}

// ---------------------------------------------------------------------------
extern "C" void kernel_launch(void* const* d_in, const int* in_sizes, int n_in,
                              void* d_out, int out_size)
{
    const float* x    = (const float*)d_in[0];
    const int*   ei   = (const int*)d_in[1];
    const float* W_in = (const float*)d_in[2];
    const float* b_in = (const float*)d_in[3];
    const float* W1   = (const float*)d_in[4];
    const float* b1   = (const float*)d_in[5];
    const float* W2   = (const float*)d_in[6];
    const float* b2   = (const float*)d_in[7];
    const float* Wc   = (const float*)d_in[8];
    const float* bc   = (const float*)d_in[9];
    float*       out  = (float*)d_out;

    void *pP, *pQ, *pcnt, *pWin, *pW1a, *pW1b, *pW2, *phF, *psF;
    cudaGetSymbolAddress(&pP,   g_P);
    cudaGetSymbolAddress(&pQ,   g_Q);
    cudaGetSymbolAddress(&pcnt, g_cnt);
    cudaGetSymbolAddress(&pWin, g_iWin);
    cudaGetSymbolAddress(&pW1a, g_iW1a);
    cudaGetSymbolAddress(&pW1b, g_iW1b);
    cudaGetSymbolAddress(&pW2,  g_iW2);
    cudaGetSymbolAddress(&phF,  g_hF);
    cudaGetSymbolAddress(&psF,  g_sF);

    const int SMEM   = 96 * 1024;
    const int SMEM_O = 96 * 1024 + 1024;
    cudaFuncSetAttribute(gemm_xa, cudaFuncAttributeMaxDynamicSharedMemorySize, SMEM);
    cudaFuncSetAttribute(gemm_pq2, cudaFuncAttributeMaxDynamicSharedMemorySize, SMEM);
    cudaFuncSetAttribute(gemm_s2o, cudaFuncAttributeMaxDynamicSharedMemorySize, SMEM_O);

    const int M = NODES;
    const int GRID = 296;

    prep_kernel<<<256, 256>>>(W_in, W1, W2);
    zero_kernel<<<256, 256>>>();
    bucket_kernel<<<(EDGES + 255) / 256, 256>>>(ei);

    // 1) h image (fp16) = relu(x @ Win + b_in)
    gemm_xa<<<GRID, 256, SMEM>>>(x, (const uint4*)pWin, b_in,
                                 (uint4*)phF, M, NT64);
    // 2+3) P = h @ W1a + b1 (fp32) ; Q = h @ W1b (fp16)
    gemm_pq2<<<GRID, 256, SMEM>>>((const uint4*)phF, (const uint4*)pW1a,
                                  (const uint4*)pW1b, b1,
                                  (float*)pP, (__half*)pQ, M, NT64);
    // 4) S image (fp16) = sum_e relu(P[d]+Q[s])
    node_kernel<<<(NODES * 32 + 255) / 256, 256>>>();
    fixup_kernel<<<1, 32>>>();
    // 5+6) out = relu(S @ W2 + deg*b2) @ Wc + bc   (fused)
    gemm_s2o<<<GRID, 256, SMEM_O>>>((const uint4*)psF, (const uint4*)pW2,
                                    b2, (const int*)pcnt, Wc, bc, out, M, NT64);
}

// round 16
// speedup vs baseline: 1.9837x; 1.0714x over previous
#include <cuda_runtime.h>
#include <cuda_fp16.h>
#include <cstdint>

#define NODES 50000
#define EDGES 800000
#define HID   128
#define CAP   128
#define OVFMAX 65536
#define NT64    782           // ceil(50000/64)  (GEMM tiles / image blocks)

// ---------------------------------------------------------------------------
// Device-global scratch (no allocations allowed)
// ---------------------------------------------------------------------------
__device__ float  g_P[(size_t)NODES * HID];
__device__ __half g_Q[(size_t)NODES * HID];
__device__ int    g_cnt[NODES];
__device__ int    g_bucket[(size_t)NODES * CAP];
__device__ int2   g_ovf[OVFMAX];
__device__ int    g_novf;

// fp16 single-image arrays: per 64-row tile, 16 KB contiguous; element (r,k)
// at byte off = r*256 + ((k>>6)<<7) + (((k&63)<<1) ^ ((r&7)<<4)).
__device__ uint4 g_hF[(size_t)NT64 * 1024];
__device__ uint4 g_sF[(size_t)NT64 * 1024];

// Weight images (transposed). Win/W2: fp16 hi 32KB + lo 32KB.
// W1: single fp16, [W1a 32KB][W1b 32KB].
__device__ uint4 g_iWin[4096];
__device__ uint4 g_iW1s[4096];
__device__ uint4 g_iW2 [4096];

// ---------------------------------------------------------------------------
__device__ __forceinline__ uint32_t smem_u32(const void* p) {
    uint32_t a;
    asm("{ .reg .u64 t; cvta.to.shared.u64 t, %1; cvt.u32.u64 %0, t; }"
        : "=r"(a) : "l"(p));
    return a;
}
__device__ __forceinline__ unsigned packh2(float x, float y) {
    __half2 t = __floats2half2_rn(x, y);
    return *reinterpret_cast<unsigned*>(&t);
}
__device__ __forceinline__ void ldsm4(unsigned* r, uint32_t addr) {
    asm volatile("ldmatrix.sync.aligned.m8n8.x4.shared.b16 {%0,%1,%2,%3}, [%4];"
                 : "=r"(r[0]), "=r"(r[1]), "=r"(r[2]), "=r"(r[3]) : "r"(addr));
}
__device__ __forceinline__ void mmah(float* d, const unsigned* a,
                                     unsigned b0, unsigned b1) {
    asm volatile(
        "mma.sync.aligned.m16n8k16.row.col.f32.f16.f16.f32 "
        "{%0,%1,%2,%3},{%4,%5,%6,%7},{%8,%9},{%0,%1,%2,%3};"
        : "+f"(d[0]), "+f"(d[1]), "+f"(d[2]), "+f"(d[3])
        : "r"(a[0]), "r"(a[1]), "r"(a[2]), "r"(a[3]), "r"(b0), "r"(b1));
}
__device__ __forceinline__ void cpa16(uint32_t dst, const void* src) {
    asm volatile("cp.async.cg.shared.global [%0], [%1], 16;"
                 :: "r"(dst), "l"(src));
}
__device__ __forceinline__ void cpa16z(uint32_t dst, const void* src, int sz) {
    asm volatile("cp.async.cg.shared.global [%0], [%1], 16, %2;"
                 :: "r"(dst), "l"(src), "r"(sz));
}
#define CP_COMMIT() asm volatile("cp.async.commit_group;" ::: "memory")
#define CP_WAIT0()  asm volatile("cp.async.wait_group 0;" ::: "memory")

__device__ __forceinline__ uint32_t img_off(int r, int k) {
    return (uint32_t)r * 256 + ((k >> 6) << 7) + ((((k & 63) << 1)) ^ ((r & 7) << 4));
}
__device__ __forceinline__ uint32_t f32_off(int r, int cc) {
    return (uint32_t)r * 512 +
           (((uint32_t)cc * 16) ^ ((r & 7) << 4) ^ ((cc >> 3) << 4));
}

// ---------------------------------------------------------------------------
// Prep: weight images + zero counters
// ---------------------------------------------------------------------------
__device__ __forceinline__ void img_write(uint4* img, int n, int k, float v) {
    __half hi = __float2half_rn(v);
    __half lo = __float2half_rn(v - __half2float(hi));
    uint32_t off = img_off(n, k);
    __half* p = (__half*)img;
    p[off >> 1]               = hi;
    p[128 * 128 + (off >> 1)] = lo;
}
__device__ __forceinline__ void img_write_s(uint4* img, int blk, int n, int k,
                                            float v) {
    __half* p = (__half*)img + blk * 128 * 128;
    p[img_off(n, k) >> 1] = __float2half_rn(v);
}

__global__ void __launch_bounds__(256)
prep_kernel(const float* __restrict__ W_in, const float* __restrict__ W1,
            const float* __restrict__ W2)
{
    int idx = blockIdx.x * blockDim.x + threadIdx.x;
    int n = (idx >> 7) & 127, k = idx & 127;
    if (idx < 16384) {
        img_write(g_iWin, n, k, W_in[k * 128 + n]);
    } else if (idx < 32768) {
        img_write_s(g_iW1s, 0, n, k, W1[k * 128 + n]);
    } else if (idx < 49152) {
        img_write_s(g_iW1s, 1, n, k, W1[(128 + k) * 128 + n]);
    } else if (idx < 65536) {
        img_write(g_iW2, n, k, W2[k * 128 + n]);
    }
    if (idx < NODES) g_cnt[idx] = 0;
    if (idx == 0) g_novf = 0;
}

// ---------------------------------------------------------------------------
// fp16 hi/lo mainloop: per k-step 6 ldsm4 (a, Wh, Wl), 16 HMMAs.
// CTA tile 64x128, 8 warps of 32x32.
// ---------------------------------------------------------------------------
__device__ __forceinline__ void tile_ml16(
    float acc[2][4][4], uint32_t aImg, uint32_t bHi, uint32_t bLo,
    int warpM, int warpN, int fi, int fswz, int fk8)
{
#pragma unroll
    for (int mt = 0; mt < 2; ++mt)
#pragma unroll
        for (int ns = 0; ns < 4; ++ns)
#pragma unroll
            for (int e = 0; e < 4; ++e) acc[mt][ns][e] = 0.f;

#pragma unroll
    for (int ks = 0; ks < 8; ++ks) {
        const int k8 = ks * 16 + fk8;
        const uint32_t koff = ((k8 >> 6) << 7) + (((k8 & 63) << 1) ^ fswz);
        unsigned a[2][4], bh[2][4], bl[2][4];
#pragma unroll
        for (int mt = 0; mt < 2; ++mt)
            ldsm4(a[mt], aImg + (uint32_t)(warpM * 32 + mt * 16 + fi) * 256 + koff);
#pragma unroll
        for (int nt = 0; nt < 2; ++nt) {
            uint32_t rb = (uint32_t)(warpN * 32 + nt * 16 + fi) * 256 + koff;
            ldsm4(bh[nt], bHi + rb);
            ldsm4(bl[nt], bLo + rb);
        }
#pragma unroll
        for (int mt = 0; mt < 2; ++mt)
#pragma unroll
            for (int nt = 0; nt < 2; ++nt) {
                mmah(acc[mt][nt * 2],     a[mt], bh[nt][0], bh[nt][2]);
                mmah(acc[mt][nt * 2 + 1], a[mt], bh[nt][1], bh[nt][3]);
                mmah(acc[mt][nt * 2],     a[mt], bl[nt][0], bl[nt][2]);
                mmah(acc[mt][nt * 2 + 1], a[mt], bl[nt][1], bl[nt][3]);
            }
    }
}

// Single-fp16-W mainloop: per k-step 4 ldsm4, 8 HMMAs.
__device__ __forceinline__ void tile_ml16s(
    float acc[2][4][4], uint32_t aImg, uint32_t bImg,
    int warpM, int warpN, int fi, int fswz, int fk8)
{
#pragma unroll
    for (int mt = 0; mt < 2; ++mt)
#pragma unroll
        for (int ns = 0; ns < 4; ++ns)
#pragma unroll
            for (int e = 0; e < 4; ++e) acc[mt][ns][e] = 0.f;

#pragma unroll
    for (int ks = 0; ks < 8; ++ks) {
        const int k8 = ks * 16 + fk8;
        const uint32_t koff = ((k8 >> 6) << 7) + (((k8 & 63) << 1) ^ fswz);
        unsigned a[2][4], b[2][4];
#pragma unroll
        for (int mt = 0; mt < 2; ++mt)
            ldsm4(a[mt], aImg + (uint32_t)(warpM * 32 + mt * 16 + fi) * 256 + koff);
#pragma unroll
        for (int nt = 0; nt < 2; ++nt)
            ldsm4(b[nt], bImg + (uint32_t)(warpN * 32 + nt * 16 + fi) * 256 + koff);
#pragma unroll
        for (int mt = 0; mt < 2; ++mt)
#pragma unroll
            for (int nt = 0; nt < 2; ++nt) {
                mmah(acc[mt][nt * 2],     a[mt], b[nt][0], b[nt][2]);
                mmah(acc[mt][nt * 2 + 1], a[mt], b[nt][1], b[nt][3]);
            }
    }
}

// ---------------------------------------------------------------------------
// gemm_xa: fp32 x (64-row tiles) via cp.async; convert to fp16 image in smem;
// hi/lo mainloop; epilogue -> relu+bias -> gmem fp16 image.
// smem: [buf 32K][W 64K] = 96 KB -> 2 CTAs/SM.
// ---------------------------------------------------------------------------
__global__ void __launch_bounds__(256, 2)
gemm_xa(const float* __restrict__ A, const uint4* __restrict__ Wimg,
        const float* __restrict__ bias, uint4* __restrict__ outF,
        int M, int ntiles)
{
    extern __shared__ char smem[];
    const uint32_t sb = smem_u32(smem);
    const uint32_t sW = sb + 32768;

    const int tid = threadIdx.x;
    const int wid = tid >> 5;
    const int L   = tid & 31;
    const int warpM = wid >> 2, warpN = wid & 3;
    const int fi = L & 15, fswz = (fi & 7) << 4, fk8 = (L >> 4) * 8;
    const int sr = tid >> 2, sq = tid & 3;

    for (int i = tid; i < 4096; i += 256) cpa16(sW + i * 16, Wimg + i);
    {
        int m0 = blockIdx.x * 64;
        for (int i = tid; i < 2048; i += 256) {
            int r = i >> 5, cc = i & 31;
            int gr = m0 + r;
            int sz = (gr < M) ? 16 : 0;
            const float* src = A + (size_t)(gr < M ? gr : 0) * 128 + cc * 4;
            cpa16z(sb + f32_off(r, cc), src, sz);
        }
    }
    CP_COMMIT();

    for (int tile = blockIdx.x; tile < ntiles; tile += gridDim.x) {
        CP_WAIT0();
        __syncthreads();

        float4 v[8];
#pragma unroll
        for (int j = 0; j < 8; ++j)
            v[j] = *(const float4*)(smem + f32_off(sr, sq * 8 + j));
        __syncthreads();

#pragma unroll
        for (int j = 0; j < 8; ++j) {
            float4 a = v[j];
            uint32_t off = img_off(sr, (sq * 8 + j) * 4);
            *(uint2*)(smem + off) =
                make_uint2(packh2(a.x, a.y), packh2(a.z, a.w));
        }
        __syncthreads();

        float acc[2][4][4];
        tile_ml16(acc, sb, sW, sW + 32768, warpM, warpN, fi, fswz, fk8);

        const int m0 = tile * 64;
        char* fB = (char*)outF + (size_t)tile * 16384;
#pragma unroll
        for (int mt = 0; mt < 2; ++mt) {
            int r0 = warpM * 32 + mt * 16 + (L >> 2);
            int r1 = r0 + 8;
#pragma unroll
            for (int ns = 0; ns < 4; ++ns) {
                int c = warpN * 32 + ns * 8 + (L & 3) * 2;
                float b0 = bias[c], b1 = bias[c + 1];
                float v00 = fmaxf(acc[mt][ns][0] + b0, 0.f);
                float v01 = fmaxf(acc[mt][ns][1] + b1, 0.f);
                float v10 = fmaxf(acc[mt][ns][2] + b0, 0.f);
                float v11 = fmaxf(acc[mt][ns][3] + b1, 0.f);
                if (m0 + r0 < M)
                    *(unsigned*)(fB + img_off(r0, c)) = packh2(v00, v01);
                if (m0 + r1 < M)
                    *(unsigned*)(fB + img_off(r1, c)) = packh2(v10, v11);
            }
        }
        __syncthreads();

        int nxt = tile + gridDim.x;
        if (nxt < ntiles) {
            int m0n = nxt * 64;
            for (int i = tid; i < 2048; i += 256) {
                int r = i >> 5, cc = i & 31;
                int gr = m0n + r;
                int sz = (gr < M) ? 16 : 0;
                const float* src = A + (size_t)(gr < M ? gr : 0) * 128 + cc * 4;
                cpa16z(sb + f32_off(r, cc), src, sz);
            }
        }
        CP_COMMIT();
    }
}

// ---------------------------------------------------------------------------
// gemm_pq: single pass over h. A tile staged once; W1a+W1b (single fp16)
// resident in 64K. Two light mainloops -> P (fp32,+b1), Q (fp16).
// smem: [A0 16K][A1 16K][W1a 32K|W1b 32K] = 96 KB -> 2 CTAs/SM.
// ---------------------------------------------------------------------------
__global__ void __launch_bounds__(256, 2)
gemm_pq(const uint4* __restrict__ aImgG, const uint4* __restrict__ Wab,
        const float* __restrict__ b1, float* __restrict__ P,
        __half* __restrict__ Q, int M, int ntiles)
{
    extern __shared__ char smem[];
    const uint32_t sb = smem_u32(smem);
    const uint32_t sW = sb + 32768;

    const int tid = threadIdx.x;
    const int wid = tid >> 5;
    const int L   = tid & 31;
    const int warpM = wid >> 2, warpN = wid & 3;
    const int fi = L & 15, fswz = (fi & 7) << 4, fk8 = (L >> 4) * 8;

    for (int i = tid; i < 4096; i += 256) cpa16(sW + i * 16, Wab + i);
    {
        const uint4* srcA = aImgG + (size_t)blockIdx.x * 1024;
        for (int i = tid; i < 1024; i += 256) cpa16(sb + i * 16, srcA + i);
    }
    CP_COMMIT();

    int cur = 0;
    for (int tile = blockIdx.x; tile < ntiles; tile += gridDim.x) {
        CP_WAIT0();
        __syncthreads();

        int nxt = tile + gridDim.x;
        if (nxt < ntiles) {
            uint32_t dst = sb + (cur ^ 1) * 16384;
            const uint4* srcA = aImgG + (size_t)nxt * 1024;
            for (int i = tid; i < 1024; i += 256) cpa16(dst + i * 16, srcA + i);
        }
        CP_COMMIT();

        const uint32_t sA = sb + cur * 16384;
        const int m0 = tile * 64;
        float acc[2][4][4];

        // P = h @ W1a + b1 (fp32)
        tile_ml16s(acc, sA, sW, warpM, warpN, fi, fswz, fk8);
#pragma unroll
        for (int mt = 0; mt < 2; ++mt) {
            int gr0 = m0 + warpM * 32 + mt * 16 + (L >> 2);
            int gr1 = gr0 + 8;
#pragma unroll
            for (int ns = 0; ns < 4; ++ns) {
                int c = warpN * 32 + ns * 8 + (L & 3) * 2;
                float b0 = b1[c], bb1 = b1[c + 1];
                if (gr0 < M)
                    *(float2*)(P + (size_t)gr0 * 128 + c) =
                        make_float2(acc[mt][ns][0] + b0, acc[mt][ns][1] + bb1);
                if (gr1 < M)
                    *(float2*)(P + (size_t)gr1 * 128 + c) =
                        make_float2(acc[mt][ns][2] + b0, acc[mt][ns][3] + bb1);
            }
        }

        // Q = h @ W1b (fp16)
        tile_ml16s(acc, sA, sW + 32768, warpM, warpN, fi, fswz, fk8);
#pragma unroll
        for (int mt = 0; mt < 2; ++mt) {
            int gr0 = m0 + warpM * 32 + mt * 16 + (L >> 2);
            int gr1 = gr0 + 8;
#pragma unroll
            for (int ns = 0; ns < 4; ++ns) {
                int c = warpN * 32 + ns * 8 + (L & 3) * 2;
                if (gr0 < M)
                    *(unsigned*)(Q + (size_t)gr0 * 128 + c) =
                        packh2(acc[mt][ns][0], acc[mt][ns][1]);
                if (gr1 < M)
                    *(unsigned*)(Q + (size_t)gr1 * 128 + c) =
                        packh2(acc[mt][ns][2], acc[mt][ns][3]);
            }
        }
        cur ^= 1;
    }
}

// ---------------------------------------------------------------------------
// gemm_s2o: S image @ W2 (hi/lo) -> relu(.+deg*b2) -> @Wc + bc -> out.
// Fused GEMV epilogue. Double-buffered A.
// smem: [A0 16K][A1 16K][W 64K][sOut 512B].
// ---------------------------------------------------------------------------
__global__ void __launch_bounds__(256, 2)
gemm_s2o(const uint4* __restrict__ aImgG, const uint4* __restrict__ Wimg,
         const float* __restrict__ b2, const int* __restrict__ rowcnt,
         const float* __restrict__ Wc, const float* __restrict__ bc,
         float* __restrict__ out, int M, int ntiles)
{
    extern __shared__ char smem[];
    const uint32_t sb = smem_u32(smem);
    const uint32_t sW = sb + 32768;
    float* sOut = (float*)(smem + 98304);

    const int tid = threadIdx.x;
    const int wid = tid >> 5;
    const int L   = tid & 31;
    const int warpM = wid >> 2, warpN = wid & 3;
    const int fi = L & 15, fswz = (fi & 7) << 4, fk8 = (L >> 4) * 8;

    for (int i = tid; i < 4096; i += 256) cpa16(sW + i * 16, Wimg + i);
    {
        int t0 = blockIdx.x;
        if (t0 < ntiles) {
            const uint4* srcA = aImgG + (size_t)t0 * 1024;
            for (int i = tid; i < 1024; i += 256) cpa16(sb + i * 16, srcA + i);
        }
    }
    CP_COMMIT();

    int cur = 0;
    for (int tile = blockIdx.x; tile < ntiles; tile += gridDim.x) {
        CP_WAIT0();
        __syncthreads();

        int nxt = tile + gridDim.x;
        if (nxt < ntiles) {
            uint32_t dst = sb + (cur ^ 1) * 16384;
            const uint4* srcA = aImgG + (size_t)nxt * 1024;
            for (int i = tid; i < 1024; i += 256) cpa16(dst + i * 16, srcA + i);
        }
        CP_COMMIT();

        float acc[2][4][4];
        tile_ml16(acc, sb + cur * 16384, sW, sW + 32768,
                  warpM, warpN, fi, fswz, fk8);

        if (tid < 128) sOut[tid] = 0.f;
        __syncthreads();

        const int m0 = tile * 64;
#pragma unroll
        for (int mt = 0; mt < 2; ++mt) {
            int gr0 = m0 + warpM * 32 + mt * 16 + (L >> 2);
            int gr1 = gr0 + 8;
            float sc0 = (gr0 < M) ? (float)rowcnt[gr0] : 0.f;
            float sc1 = (gr1 < M) ? (float)rowcnt[gr1] : 0.f;
            float p00 = 0.f, p01 = 0.f, p10 = 0.f, p11 = 0.f;
#pragma unroll
            for (int ns = 0; ns < 4; ++ns) {
                int c = warpN * 32 + ns * 8 + (L & 3) * 2;
                float b0 = b2[c], b1 = b2[c + 1];
                float v00 = fmaxf(acc[mt][ns][0] + sc0 * b0, 0.f);
                float v01 = fmaxf(acc[mt][ns][1] + sc0 * b1, 0.f);
                float v10 = fmaxf(acc[mt][ns][2] + sc1 * b0, 0.f);
                float v11 = fmaxf(acc[mt][ns][3] + sc1 * b1, 0.f);
                float2 w0 = *(const float2*)(Wc + c * 2);
                float2 w1 = *(const float2*)(Wc + (c + 1) * 2);
                p00 += v00 * w0.x + v01 * w1.x;
                p01 += v00 * w0.y + v01 * w1.y;
                p10 += v10 * w0.x + v11 * w1.x;
                p11 += v10 * w0.y + v11 * w1.y;
            }
#pragma unroll
            for (int off = 1; off <= 2; off <<= 1) {
                p00 += __shfl_xor_sync(0xffffffffu, p00, off);
                p01 += __shfl_xor_sync(0xffffffffu, p01, off);
                p10 += __shfl_xor_sync(0xffffffffu, p10, off);
                p11 += __shfl_xor_sync(0xffffffffu, p11, off);
            }
            if ((L & 3) == 0) {
                int r0 = warpM * 32 + mt * 16 + (L >> 2);
                atomicAdd(&sOut[r0 * 2],           p00);
                atomicAdd(&sOut[r0 * 2 + 1],       p01);
                atomicAdd(&sOut[(r0 + 8) * 2],     p10);
                atomicAdd(&sOut[(r0 + 8) * 2 + 1], p11);
            }
        }
        __syncthreads();

        if (tid < 128) {
            int r = tid >> 1, k = tid & 1;
            int gr = m0 + r;
            if (gr < M) out[(size_t)gr * 2 + k] = sOut[tid] + bc[k];
        }
        cur ^= 1;
    }
}

// ---------------------------------------------------------------------------
__global__ void __launch_bounds__(256)
bucket_kernel(const int* __restrict__ ei)
{
    int e = blockIdx.x * blockDim.x + threadIdx.x;
    if (e >= EDGES) return;
    int s = ei[e];
    int d = ei[EDGES + e];
    int slot = atomicAdd(&g_cnt[d], 1);
    if (slot < CAP) {
        g_bucket[(size_t)d * CAP + slot] = s;
    } else {
        int o = atomicAdd(&g_novf, 1);
        if (o < OVFMAX) g_ovf[o] = make_int2(s, d);
    }
}

// Warp per node: S[d] = sum relu(P[d]+Q[src]); write S as fp16 image.
__global__ void __launch_bounds__(256)
node_kernel()
{
    int d    = (blockIdx.x * blockDim.x + threadIdx.x) >> 5;
    int lane = threadIdx.x & 31;
    if (d >= NODES) return;

    int n = g_cnt[d];
    if (n > CAP) n = CAP;

    float4 p = ((const float4*)(g_P + (size_t)d * HID))[lane];
    float4 acc = make_float4(0.f, 0.f, 0.f, 0.f);
    const int* bkt = g_bucket + (size_t)d * CAP;
#pragma unroll 2
    for (int i = 0; i < n; ++i) {
        int s = __ldg(bkt + i);
        uint2 qraw = ((const uint2*)(g_Q + (size_t)s * HID))[lane];
        __half2 q0 = *(__half2*)&qraw.x;
        __half2 q1 = *(__half2*)&qraw.y;
        float2 f0 = __half22float2(q0);
        float2 f1 = __half22float2(q1);
        acc.x += fmaxf(p.x + f0.x, 0.f);
        acc.y += fmaxf(p.y + f0.y, 0.f);
        acc.z += fmaxf(p.z + f1.x, 0.f);
        acc.w += fmaxf(p.w + f1.y, 0.f);
    }
    int r = d & 63;
    char* base = (char*)g_sF + (size_t)(d >> 6) * 16384;
    *(uint2*)(base + img_off(r, lane * 4)) =
        make_uint2(packh2(acc.x, acc.y), packh2(acc.z, acc.w));
}

// Serial overflow fixup (single warp; expected empty). RMW on S image.
__global__ void __launch_bounds__(32)
fixup_kernel()
{
    int total = g_novf;
    if (total > OVFMAX) total = OVFMAX;
    int lane = threadIdx.x;
    for (int j = 0; j < total; ++j) {
        int2 e = g_ovf[j];
        float4 p = ((const float4*)(g_P + (size_t)e.y * HID))[lane];
        uint2 qraw = ((const uint2*)(g_Q + (size_t)e.x * HID))[lane];
        __half2 q0 = *(__half2*)&qraw.x;
        __half2 q1 = *(__half2*)&qraw.y;
        float2 f0 = __half22float2(q0);
        float2 f1 = __half22float2(q1);
        int r = e.y & 63;
        char* base = (char*)g_sF + (size_t)(e.y >> 6) * 16384;
        uint2 sv = *(uint2*)(base + img_off(r, lane * 4));
        __half2 s0 = *(__half2*)&sv.x;
        __half2 s1 = *(__half2*)&sv.y;
        float vx = __half2float(s0.x) + fmaxf(p.x + f0.x, 0.f);
        float vy = __half2float(s0.y) + fmaxf(p.y + f0.y, 0.f);
        float vz = __half2float(s1.x) + fmaxf(p.z + f1.x, 0.f);
        float vw = __half2float(s1.y) + fmaxf(p.w + f1.y, 0.f);
        *(uint2*)(base + img_off(r, lane * 4)) =
            make_uint2(packh2(vx, vy), packh2(vz, vw));
        __syncwarp();
    }
}

// ---------------------------------------------------------------------------
extern "C" void kernel_launch(void* const* d_in, const int* in_sizes, int n_in,
                              void* d_out, int out_size)
{
    const float* x    = (const float*)d_in[0];
    const int*   ei   = (const int*)d_in[1];
    const float* W_in = (const float*)d_in[2];
    const float* b_in = (const float*)d_in[3];
    const float* W1   = (const float*)d_in[4];
    const float* b1   = (const float*)d_in[5];
    const float* W2   = (const float*)d_in[6];
    const float* b2   = (const float*)d_in[7];
    const float* Wc   = (const float*)d_in[8];
    const float* bc   = (const float*)d_in[9];
    float*       out  = (float*)d_out;

    void *pP, *pQ, *pcnt, *pWin, *pW1s, *pW2, *phF, *psF;
    cudaGetSymbolAddress(&pP,   g_P);
    cudaGetSymbolAddress(&pQ,   g_Q);
    cudaGetSymbolAddress(&pcnt, g_cnt);
    cudaGetSymbolAddress(&pWin, g_iWin);
    cudaGetSymbolAddress(&pW1s, g_iW1s);
    cudaGetSymbolAddress(&pW2,  g_iW2);
    cudaGetSymbolAddress(&phF,  g_hF);
    cudaGetSymbolAddress(&psF,  g_sF);

    const int SMEM   = 96 * 1024;
    const int SMEM_O = 96 * 1024 + 1024;
    cudaFuncSetAttribute(gemm_xa, cudaFuncAttributeMaxDynamicSharedMemorySize, SMEM);
    cudaFuncSetAttribute(gemm_pq, cudaFuncAttributeMaxDynamicSharedMemorySize, SMEM);
    cudaFuncSetAttribute(gemm_s2o, cudaFuncAttributeMaxDynamicSharedMemorySize, SMEM_O);

    const int M = NODES;
    const int GRID = 296;

    prep_kernel<<<256, 256>>>(W_in, W1, W2);
    bucket_kernel<<<(EDGES + 255) / 256, 256>>>(ei);

    // 1) h image (fp16) = relu(x @ Win + b_in)
    gemm_xa<<<GRID, 256, SMEM>>>(x, (const uint4*)pWin, b_in,
                                 (uint4*)phF, M, NT64);
    // 2) P = h @ W1a + b1 (fp32) ; Q = h @ W1b (fp16)  [one A pass]
    gemm_pq<<<GRID, 256, SMEM>>>((const uint4*)phF, (const uint4*)pW1s, b1,
                                 (float*)pP, (__half*)pQ, M, NT64);
    // 3) S image (fp16) = sum_e relu(P[d]+Q[s])
    node_kernel<<<(NODES * 32 + 255) / 256, 256>>>();
    fixup_kernel<<<1, 32>>>();
    // 4+5) out = relu(S @ W2 + deg*b2) @ Wc + bc   (fused)
    gemm_s2o<<<GRID, 256, SMEM_O>>>((const uint4*)psF, (const uint4*)pW2,
                                    b2, (const int*)pcnt, Wc, bc, out, M, NT64);
}